// round 13
// baseline (speedup 1.0000x reference)
#include <cuda_runtime.h>
#include <cuda_bf16.h>
#include <math.h>
#include <stdint.h>

#define BATCH 4
#define SEQ   2048
#define DMODEL 1024
#define NHEAD 16
#define HDIM  64
#define MTOT  8192          // BATCH*SEQ
#define KSP   2048          // 2*DMODEL (hi|lo)

// ---------------- scratch (device globals) ----------------
__device__ __nv_bfloat16 g_xs[MTOT * KSP];                   // x split  [M][2048]
__device__ __nv_bfloat16 g_wtq[DMODEL * KSP];                // W^T split [N][2048]
__device__ __nv_bfloat16 g_wtk[DMODEL * KSP];
__device__ __nv_bfloat16 g_wtv[DMODEL * KSP];
__device__ __nv_bfloat16 g_wto[DMODEL * KSP];
__device__ __nv_bfloat16 g_qsp[BATCH * NHEAD * SEQ * 2 * HDIM]; // [B,H,S,128] hi|lo
__device__ __nv_bfloat16 g_ksp[BATCH * NHEAD * SEQ * 2 * HDIM];
__device__ __nv_bfloat16 g_vsp[BATCH * NHEAD * SEQ * 2 * HDIM];
__device__ __nv_bfloat16 g_cs[MTOT * KSP];                   // ctx split [M][2048]

// ---------------- helpers ----------------
__device__ __forceinline__ uint32_t smem_u32(const void* p) {
    return (uint32_t)__cvta_generic_to_shared(p);
}
__device__ __forceinline__ void cp16(uint32_t s, const void* g) {
    asm volatile("cp.async.cg.shared.global [%0], [%1], 16;" :: "r"(s), "l"(g));
}
__device__ __forceinline__ void cp_commit() {
    asm volatile("cp.async.commit_group;" ::: "memory");
}
__device__ __forceinline__ void cp_wait1() {
    asm volatile("cp.async.wait_group 1;" ::: "memory");
}
__device__ __forceinline__ void cp_wait0() {
    asm volatile("cp.async.wait_group 0;" ::: "memory");
}
__device__ __forceinline__ void ldsm_x4(uint32_t& r0, uint32_t& r1, uint32_t& r2, uint32_t& r3, uint32_t a) {
    asm volatile("ldmatrix.sync.aligned.m8n8.x4.shared.b16 {%0,%1,%2,%3},[%4];"
                 : "=r"(r0), "=r"(r1), "=r"(r2), "=r"(r3) : "r"(a));
}
__device__ __forceinline__ void ldsm_x4t(uint32_t& r0, uint32_t& r1, uint32_t& r2, uint32_t& r3, uint32_t a) {
    asm volatile("ldmatrix.sync.aligned.m8n8.x4.trans.shared.b16 {%0,%1,%2,%3},[%4];"
                 : "=r"(r0), "=r"(r1), "=r"(r2), "=r"(r3) : "r"(a));
}
__device__ __forceinline__ void mma16816(float* c, const uint32_t* a, const uint32_t* b) {
    asm volatile(
        "mma.sync.aligned.m16n8k16.row.col.f32.bf16.bf16.f32 "
        "{%0,%1,%2,%3},{%4,%5,%6,%7},{%8,%9},{%0,%1,%2,%3};"
        : "+f"(c[0]), "+f"(c[1]), "+f"(c[2]), "+f"(c[3])
        : "r"(a[0]), "r"(a[1]), "r"(a[2]), "r"(a[3]), "r"(b[0]), "r"(b[1]));
}
__device__ __forceinline__ void pack_pair(float x0, float x1, uint32_t& hi, uint32_t& lo) {
    uint32_t h;
    asm("cvt.rn.bf16x2.f32 %0, %1, %2;" : "=r"(h) : "f"(x1), "f"(x0));
    __nv_bfloat162 h2 = *reinterpret_cast<__nv_bfloat162*>(&h);
    float r0 = x0 - __bfloat162float(h2.x);
    float r1 = x1 - __bfloat162float(h2.y);
    uint32_t l;
    asm("cvt.rn.bf16x2.f32 %0, %1, %2;" : "=r"(l) : "f"(r1), "f"(r0));
    hi = h; lo = l;
}

// ---------------- split: fp32 [M][1024] -> bf16 [M][2048] hi|lo ----------------
__global__ __launch_bounds__(256)
void split_kernel(const float* __restrict__ in, __nv_bfloat16* __restrict__ out)
{
    int i = blockIdx.x * 256 + threadIdx.x;
    float4 x = reinterpret_cast<const float4*>(in)[i];
    int r = i >> 8;
    int c = (i & 255) * 4;
    __nv_bfloat162 h0 = __floats2bfloat162_rn(x.x, x.y);
    __nv_bfloat162 h1 = __floats2bfloat162_rn(x.z, x.w);
    __nv_bfloat162 l0 = __floats2bfloat162_rn(x.x - __bfloat162float(h0.x), x.y - __bfloat162float(h0.y));
    __nv_bfloat162 l1 = __floats2bfloat162_rn(x.z - __bfloat162float(h1.x), x.w - __bfloat162float(h1.y));
    __nv_bfloat162* oh = reinterpret_cast<__nv_bfloat162*>(&out[(long)r * KSP + c]);
    oh[0] = h0; oh[1] = h1;
    __nv_bfloat162* ol = reinterpret_cast<__nv_bfloat162*>(&out[(long)r * KSP + 1024 + c]);
    ol[0] = l0; ol[1] = l1;
}

// ---------------- fused weight split+transpose (4 weights, blockIdx.z) ----------------
__global__ void wsplit_kernel(const float* __restrict__ W0, const float* __restrict__ W1,
                              const float* __restrict__ W2, const float* __restrict__ W3,
                              __nv_bfloat16* __restrict__ T0, __nv_bfloat16* __restrict__ T1,
                              __nv_bfloat16* __restrict__ T2, __nv_bfloat16* __restrict__ T3)
{
    const float* W = (blockIdx.z == 0) ? W0 : (blockIdx.z == 1) ? W1 : (blockIdx.z == 2) ? W2 : W3;
    __nv_bfloat16* Wt = (blockIdx.z == 0) ? T0 : (blockIdx.z == 1) ? T1 : (blockIdx.z == 2) ? T2 : T3;

    __shared__ float tile[32][33];
    int n0 = blockIdx.x * 32, k0 = blockIdx.y * 32;
    int tx = threadIdx.x, ty = threadIdx.y;   // 32 x 8
#pragma unroll
    for (int j = 0; j < 4; j++)
        tile[ty + 8 * j][tx] = W[(long)(k0 + ty + 8 * j) * DMODEL + n0 + tx];
    __syncthreads();
#pragma unroll
    for (int j = 0; j < 4; j++) {
        int n = n0 + ty + 8 * j;
        int k = k0 + tx;
        float v = tile[tx][ty + 8 * j];
        __nv_bfloat16 h = __float2bfloat16(v);
        Wt[(long)n * KSP + k] = h;
        Wt[(long)n * KSP + 1024 + k] = __float2bfloat16(v - __bfloat162float(h));
    }
}

// ---------------- split-bf16 tensor-core GEMM, 128-thread CTA, 4 CTA/SM ----------------
// Tile C = 128x64, 4 warps (each 64x32). 2-stage BK=64 ring, 1 sync/step.
// OUT_MODE 0: plain fp32 [M][N]; 2: heads bf16-split; 3: heads + rope + scale
#define NSTEP 48
#define GPAD  72
#define A_ELEMS (128 * GPAD)
#define B_ELEMS (64 * GPAD)
#define STG_ELEMS (A_ELEMS + B_ELEMS)
#define GEMM_SMEM (2 * STG_ELEMS * 2)    // 55296 bytes

template <int OUT_MODE>
__global__ __launch_bounds__(128, 4)
void gemm_mma(const __nv_bfloat16* __restrict__ A,
              const __nv_bfloat16* __restrict__ Bt,
              const float* __restrict__ bias,
              void* __restrict__ Cout,
              const int* __restrict__ start_p,
              float scale)
{
    extern __shared__ __align__(16) char smem_raw[];
    __nv_bfloat16* smem = reinterpret_cast<__nv_bfloat16*>(smem_raw);

    const int tid = threadIdx.x;
    const int lane = tid & 31;
    const int wid = tid >> 5;          // 0..3
    const int warp_m = wid & 1;        // 2 warps in M (64 rows each)
    const int warp_n = wid >> 1;       // 2 warps in N (32 cols each)
    const int m0 = blockIdx.y * 128;
    const int n0 = blockIdx.x * 64;

    float acc[4][4][4];
#pragma unroll
    for (int i = 0; i < 4; i++)
#pragma unroll
        for (int j = 0; j < 4; j++)
#pragma unroll
            for (int q = 0; q < 4; q++) acc[i][j][q] = 0.f;

    // loader: A rows 0..127 (1/thread) + B rows 0..63 (threads 0..63)
    auto issue = [&](int st, int step) {
        const int seg = step >> 4;
        const int ks  = (step & 15) << 6;
        const int aoff = (seg == 1 ? 1024 : 0) + ks;
        const int boff = (seg == 2 ? 1024 : 0) + ks;
        __nv_bfloat16* base = smem + st * STG_ELEMS;
        {
            const __nv_bfloat16* ag = &A[(long)(m0 + tid) * KSP + aoff];
            const uint32_t sa = smem_u32(base + tid * GPAD);
#pragma unroll
            for (int c = 0; c < 8; c++)
                cp16(sa + c * 16, ag + c * 8);
        }
        if (tid < 64) {
            const __nv_bfloat16* bg = &Bt[(long)(n0 + tid) * KSP + boff];
            const uint32_t sb = smem_u32(base + A_ELEMS + tid * GPAD);
#pragma unroll
            for (int c = 0; c < 8; c++)
                cp16(sb + c * 16, bg + c * 8);
        }
    };

    issue(0, 0); cp_commit();

    const int mrow = warp_m * 64 + (lane & 15);
    const int kfa  = (lane >> 4) << 3;
    const int nfrag = warp_n * 32 + ((lane >> 4) << 3) + (lane & 7);
    const int kfb  = ((lane >> 3) & 1) << 3;

    for (int step = 0; step < NSTEP; step++) {
        cp_wait0();
        __syncthreads();
        if (step + 1 < NSTEP) { issue((step + 1) & 1, step + 1); cp_commit(); }

        const __nv_bfloat16* S = smem + (step & 1) * STG_ELEMS;
        const __nv_bfloat16* sA = S;
        const __nv_bfloat16* sB = S + A_ELEMS;

#pragma unroll
        for (int kk = 0; kk < 64; kk += 16) {
            uint32_t af[4][4];
#pragma unroll
            for (int mt = 0; mt < 4; mt++)
                ldsm_x4(af[mt][0], af[mt][1], af[mt][2], af[mt][3],
                        smem_u32(&sA[(mrow + mt * 16) * GPAD + kk + kfa]));
            uint32_t bfr[4][2];
#pragma unroll
            for (int bt = 0; bt < 2; bt++) {
                uint32_t r0, r1, r2, r3;
                ldsm_x4(r0, r1, r2, r3,
                        smem_u32(&sB[(nfrag + bt * 16) * GPAD + kk + kfb]));
                bfr[2 * bt][0] = r0; bfr[2 * bt][1] = r1;
                bfr[2 * bt + 1][0] = r2; bfr[2 * bt + 1][1] = r3;
            }
#pragma unroll
            for (int mt = 0; mt < 4; mt++)
#pragma unroll
                for (int nt = 0; nt < 4; nt++)
                    mma16816(acc[mt][nt], af[mt], bfr[nt]);
        }
    }

    // ---------------- epilogue ----------------
    const int r_m = warp_m * 64 + (lane >> 2);
    const int c_n = warp_n * 32 + 2 * (lane & 3);
    int start = 0;
    if (OUT_MODE == 3) start = *start_p;

#pragma unroll
    for (int mt = 0; mt < 4; mt++) {
#pragma unroll
        for (int nt = 0; nt < 4; nt++) {
            const int mg = m0 + r_m + mt * 16;
            const int ng = n0 + c_n + nt * 8;
            const float b0v = bias[ng], b1v = bias[ng + 1];
            float x0 = acc[mt][nt][0] + b0v, x1 = acc[mt][nt][1] + b1v;
            float y0 = acc[mt][nt][2] + b0v, y1 = acc[mt][nt][3] + b1v;

            if (OUT_MODE == 0) {
                float* outp = (float*)Cout;
                *(float2*)&outp[(long)mg * DMODEL + ng] = make_float2(x0, x1);
                *(float2*)&outp[(long)(mg + 8) * DMODEL + ng] = make_float2(y0, y1);
            } else {
                const int b = mg >> 11, s = mg & (SEQ - 1);
                const int h = ng >> 6, d = ng & (HDIM - 1);
                const long rowb = ((long)(b * NHEAD + h) * SEQ + s) * 128;
                __nv_bfloat16* outp = (__nv_bfloat16*)Cout;
#pragma unroll
                for (int rr = 0; rr < 2; rr++) {
                    float v0 = rr ? y0 : x0;
                    float v1 = rr ? y1 : x1;
                    int ss = s + rr * 8;
                    if (OUT_MODE == 3 && ss >= start) {
                        float pos = (float)(ss - start);
                        float invf = __expf(-(float)(d >> 1) * 0.28782313662425572f);
                        float sn, cs;
                        sincosf(pos * invf, &sn, &cs);
                        float t0 = v0 * cs - v1 * sn;
                        float t1 = v1 * cs + v0 * sn;
                        v0 = t0; v1 = t1;
                    }
                    v0 *= scale; v1 *= scale;
                    uint32_t hi, lo;
                    pack_pair(v0, v1, hi, lo);
                    long ro = rowb + (long)rr * 8 * 128;
                    *(uint32_t*)&outp[ro + d] = hi;
                    *(uint32_t*)&outp[ro + 64 + d] = lo;
                }
            }
        }
    }
}

// ---------------- flash attention (split-bf16 mma, cp.async 2-stage, 2 CTA/SM) ----------------
// [unchanged from round 10 — validated at 1304.6 µs]
#define APAD 136
#define ATTN_STAGES 2
#define ATTN_SMEM (ATTN_STAGES * 64 * APAD * 2 * 2)

__global__ __launch_bounds__(256, 2)
void attn_mma(const __nv_bfloat16* __restrict__ qs,
              const __nv_bfloat16* __restrict__ ks,
              const __nv_bfloat16* __restrict__ vs,
              __nv_bfloat16* __restrict__ cs)
{
    extern __shared__ __align__(16) char smem_raw[];
    __nv_bfloat16* sK = reinterpret_cast<__nv_bfloat16*>(smem_raw);   // [2][64][136]
    __nv_bfloat16* sV = sK + ATTN_STAGES * 64 * APAD;                 // [2][64][136]

    const int tid = threadIdx.x;
    const int lane = tid & 31;
    const int wid = tid >> 5;
    const int qb = blockIdx.x;
    const int bh = blockIdx.y;
    const long hbase = (long)bh * SEQ * 128;

    {
        const __nv_bfloat16* qg = qs + hbase + (long)qb * 128 * 128;
        const int r = tid >> 1;
        const int c = (tid & 1) * 64;
#pragma unroll
        for (int i = 0; i < 8; i++)
            *(uint4*)&sK[r * APAD + c + i * 8] = *(const uint4*)&qg[(long)r * 128 + c + i * 8];
    }
    __syncthreads();
    uint32_t qhi[4][4], qlo[4][4];
    {
        const int mrow = wid * 16 + (lane & 15);
        const int kadd = (lane >> 4) << 3;
#pragma unroll
        for (int kc = 0; kc < 4; kc++) {
            ldsm_x4(qhi[kc][0], qhi[kc][1], qhi[kc][2], qhi[kc][3],
                    smem_u32(&sK[mrow * APAD + kc * 16 + kadd]));
            ldsm_x4(qlo[kc][0], qlo[kc][1], qlo[kc][2], qlo[kc][3],
                    smem_u32(&sK[mrow * APAD + 64 + kc * 16 + kadd]));
        }
    }
    __syncthreads();

    const int ldrow  = tid >> 4;
    const int ldc16  = tid & 15;
    auto issue = [&](int st, int kt) {
        const __nv_bfloat16* kg = ks + hbase + (long)kt * 64 * 128;
        const __nv_bfloat16* vg = vs + hbase + (long)kt * 64 * 128;
        __nv_bfloat16* sKs = sK + st * 64 * APAD;
        __nv_bfloat16* sVs = sV + st * 64 * APAD;
#pragma unroll
        for (int i = 0; i < 4; i++) {
            const int r = ldrow + 16 * i;
            cp16(smem_u32(&sKs[r * APAD + ldc16 * 8]), &kg[(long)r * 128 + ldc16 * 8]);
            cp16(smem_u32(&sVs[r * APAD + ldc16 * 8]), &vg[(long)r * 128 + ldc16 * 8]);
        }
    };

    float O[8][4];
#pragma unroll
    for (int i = 0; i < 8; i++)
#pragma unroll
        for (int j = 0; j < 4; j++) O[i][j] = 0.f;
    float m0 = -1e30f, m1 = -1e30f, l0 = 0.f, l1 = 0.f;

    issue(0, 0); cp_commit();
    issue(1, 1); cp_commit();

    const int NT = SEQ / 64;
    for (int kt = 0; kt < NT; kt++) {
        if (kt >= NT - 1) cp_wait0(); else cp_wait1();
        __syncthreads();

        const int st = kt & 1;
        const __nv_bfloat16* Kst = sK + st * 64 * APAD;
        const __nv_bfloat16* Vst = sV + st * 64 * APAD;

        float S[8][4];
#pragma unroll
        for (int i = 0; i < 8; i++)
#pragma unroll
            for (int j = 0; j < 4; j++) S[i][j] = 0.f;

#pragma unroll
        for (int kc = 0; kc < 4; kc++) {
            uint32_t b4[4][4];
#pragma unroll
            for (int bt = 0; bt < 4; bt++) {
                int n = bt * 16 + ((lane >> 4) << 3) + (lane & 7);
                int kcol = kc * 16 + (((lane >> 3) & 1) << 3);
                ldsm_x4(b4[bt][0], b4[bt][1], b4[bt][2], b4[bt][3],
                        smem_u32(&Kst[n * APAD + kcol]));
            }
#pragma unroll
            for (int bt = 0; bt < 4; bt++) {
                mma16816(S[2 * bt],     qhi[kc], &b4[bt][0]);
                mma16816(S[2 * bt + 1], qhi[kc], &b4[bt][2]);
                mma16816(S[2 * bt],     qlo[kc], &b4[bt][0]);
                mma16816(S[2 * bt + 1], qlo[kc], &b4[bt][2]);
            }
        }
#pragma unroll
        for (int kc = 0; kc < 4; kc++) {
            uint32_t b4[4][4];
#pragma unroll
            for (int bt = 0; bt < 4; bt++) {
                int n = bt * 16 + ((lane >> 4) << 3) + (lane & 7);
                int kcol = 64 + kc * 16 + (((lane >> 3) & 1) << 3);
                ldsm_x4(b4[bt][0], b4[bt][1], b4[bt][2], b4[bt][3],
                        smem_u32(&Kst[n * APAD + kcol]));
            }
#pragma unroll
            for (int bt = 0; bt < 4; bt++) {
                mma16816(S[2 * bt],     qhi[kc], &b4[bt][0]);
                mma16816(S[2 * bt + 1], qhi[kc], &b4[bt][2]);
            }
        }

        float tmax0 = -1e30f, tmax1 = -1e30f;
#pragma unroll
        for (int nt = 0; nt < 8; nt++) {
            tmax0 = fmaxf(tmax0, fmaxf(S[nt][0], S[nt][1]));
            tmax1 = fmaxf(tmax1, fmaxf(S[nt][2], S[nt][3]));
        }
        tmax0 = fmaxf(tmax0, __shfl_xor_sync(0xffffffffu, tmax0, 1));
        tmax0 = fmaxf(tmax0, __shfl_xor_sync(0xffffffffu, tmax0, 2));
        tmax1 = fmaxf(tmax1, __shfl_xor_sync(0xffffffffu, tmax1, 1));
        tmax1 = fmaxf(tmax1, __shfl_xor_sync(0xffffffffu, tmax1, 2));
        const float mn0 = fmaxf(m0, tmax0);
        const float mn1 = fmaxf(m1, tmax1);
        const float corr0 = __expf(m0 - mn0);
        const float corr1 = __expf(m1 - mn1);
        m0 = mn0; m1 = mn1;
#pragma unroll
        for (int nt = 0; nt < 8; nt++) {
            O[nt][0] *= corr0; O[nt][1] *= corr0;
            O[nt][2] *= corr1; O[nt][3] *= corr1;
        }

        float sum0 = 0.f, sum1 = 0.f;
        uint32_t phi[4][4], plo[4][4];
#pragma unroll
        for (int bt = 0; bt < 4; bt++) {
            float p00 = __expf(S[2 * bt][0] - mn0), p01 = __expf(S[2 * bt][1] - mn0);
            float p02 = __expf(S[2 * bt][2] - mn1), p03 = __expf(S[2 * bt][3] - mn1);
            float p10 = __expf(S[2 * bt + 1][0] - mn0), p11 = __expf(S[2 * bt + 1][1] - mn0);
            float p12 = __expf(S[2 * bt + 1][2] - mn1), p13 = __expf(S[2 * bt + 1][3] - mn1);
            sum0 += p00 + p01 + p10 + p11;
            sum1 += p02 + p03 + p12 + p13;
            pack_pair(p00, p01, phi[bt][0], plo[bt][0]);
            pack_pair(p02, p03, phi[bt][1], plo[bt][1]);
            pack_pair(p10, p11, phi[bt][2], plo[bt][2]);
            pack_pair(p12, p13, phi[bt][3], plo[bt][3]);
        }
        sum0 += __shfl_xor_sync(0xffffffffu, sum0, 1);
        sum0 += __shfl_xor_sync(0xffffffffu, sum0, 2);
        sum1 += __shfl_xor_sync(0xffffffffu, sum1, 1);
        sum1 += __shfl_xor_sync(0xffffffffu, sum1, 2);
        l0 = l0 * corr0 + sum0;
        l1 = l1 * corr1 + sum1;

#pragma unroll
        for (int kc = 0; kc < 4; kc++) {
            uint32_t vb[4][4];
#pragma unroll
            for (int ntp = 0; ntp < 4; ntp++) {
                int key = kc * 16 + ((lane >> 3) & 1) * 8 + (lane & 7);
                int col = ntp * 16 + ((lane >> 4) << 3);
                ldsm_x4t(vb[ntp][0], vb[ntp][1], vb[ntp][2], vb[ntp][3],
                         smem_u32(&Vst[key * APAD + col]));
            }
#pragma unroll
            for (int ntp = 0; ntp < 4; ntp++) {
                mma16816(O[2 * ntp],     phi[kc], &vb[ntp][0]);
                mma16816(O[2 * ntp + 1], phi[kc], &vb[ntp][2]);
                mma16816(O[2 * ntp],     plo[kc], &vb[ntp][0]);
                mma16816(O[2 * ntp + 1], plo[kc], &vb[ntp][2]);
            }
        }
#pragma unroll
        for (int kc = 0; kc < 4; kc++) {
            uint32_t vb[4][4];
#pragma unroll
            for (int ntp = 0; ntp < 4; ntp++) {
                int key = kc * 16 + ((lane >> 3) & 1) * 8 + (lane & 7);
                int col = 64 + ntp * 16 + ((lane >> 4) << 3);
                ldsm_x4t(vb[ntp][0], vb[ntp][1], vb[ntp][2], vb[ntp][3],
                         smem_u32(&Vst[key * APAD + col]));
            }
#pragma unroll
            for (int ntp = 0; ntp < 4; ntp++) {
                mma16816(O[2 * ntp],     phi[kc], &vb[ntp][0]);
                mma16816(O[2 * ntp + 1], phi[kc], &vb[ntp][2]);
            }
        }

        __syncthreads();
        if (kt + 2 < NT) { issue(st, kt + 2); cp_commit(); }
    }

    const float inv0 = 1.f / l0;
    const float inv1 = 1.f / l1;
    const int b = bh >> 4, h = bh & 15;
    const int s0 = qb * 128 + wid * 16 + (lane >> 2);
    const long row0 = (long)(b * SEQ + s0) * KSP;
    const long row1 = row0 + (long)8 * KSP;
#pragma unroll
    for (int nt = 0; nt < 8; nt++) {
        int c = h * HDIM + nt * 8 + 2 * (lane & 3);
        uint32_t hi, lo;
        pack_pair(O[nt][0] * inv0, O[nt][1] * inv0, hi, lo);
        *(uint32_t*)&cs[row0 + c] = hi;
        *(uint32_t*)&cs[row0 + 1024 + c] = lo;
        pack_pair(O[nt][2] * inv1, O[nt][3] * inv1, hi, lo);
        *(uint32_t*)&cs[row1 + c] = hi;
        *(uint32_t*)&cs[row1 + 1024 + c] = lo;
    }
}

// ---------------- launch ----------------
extern "C" void kernel_launch(void* const* d_in, const int* in_sizes, int n_in,
                              void* d_out, int out_size)
{
    const float* x  = (const float*)d_in[0];
    const float* Wq = (const float*)d_in[1];
    const float* bq = (const float*)d_in[2];
    const float* Wk = (const float*)d_in[3];
    const float* bk = (const float*)d_in[4];
    const float* Wv = (const float*)d_in[5];
    const float* bv = (const float*)d_in[6];
    const float* Wo = (const float*)d_in[7];
    const float* bo = (const float*)d_in[8];
    const int* rope_start = (const int*)d_in[9];
    float* out = (float*)d_out;

    __nv_bfloat16 *xs, *wtq, *wtk, *wtv, *wto, *qsp, *ksp, *vsp, *cs;
    cudaGetSymbolAddress((void**)&xs,  g_xs);
    cudaGetSymbolAddress((void**)&wtq, g_wtq);
    cudaGetSymbolAddress((void**)&wtk, g_wtk);
    cudaGetSymbolAddress((void**)&wtv, g_wtv);
    cudaGetSymbolAddress((void**)&wto, g_wto);
    cudaGetSymbolAddress((void**)&qsp, g_qsp);
    cudaGetSymbolAddress((void**)&ksp, g_ksp);
    cudaGetSymbolAddress((void**)&vsp, g_vsp);
    cudaGetSymbolAddress((void**)&cs,  g_cs);

    static bool attr_done = false;
    if (!attr_done) {
        cudaFuncSetAttribute(gemm_mma<0>, cudaFuncAttributeMaxDynamicSharedMemorySize, GEMM_SMEM);
        cudaFuncSetAttribute(gemm_mma<2>, cudaFuncAttributeMaxDynamicSharedMemorySize, GEMM_SMEM);
        cudaFuncSetAttribute(gemm_mma<3>, cudaFuncAttributeMaxDynamicSharedMemorySize, GEMM_SMEM);
        cudaFuncSetAttribute(attn_mma,    cudaFuncAttributeMaxDynamicSharedMemorySize, ATTN_SMEM);
        attr_done = true;
    }

    // 1: input split
    split_kernel<<<MTOT, 256>>>(x, xs);
    // 2: fused weight splits
    dim3 wgrid(32, 32, 4), wblock(32, 8);
    wsplit_kernel<<<wgrid, wblock>>>(Wq, Wk, Wv, Wo, wtq, wtk, wtv, wto);

    // 3-5: projections (128-thread CTAs, tile 128x64, 4 CTA/SM)
    dim3 ggrid(DMODEL / 64, MTOT / 128);     // (16, 64) = 1024 blocks
    gemm_mma<3><<<ggrid, 128, GEMM_SMEM>>>(xs, wtq, bq, qsp, rope_start, 0.125f);
    gemm_mma<3><<<ggrid, 128, GEMM_SMEM>>>(xs, wtk, bk, ksp, rope_start, 1.0f);
    gemm_mma<2><<<ggrid, 128, GEMM_SMEM>>>(xs, wtv, bv, vsp, rope_start, 1.0f);

    // 6: attention (2-stage, 2 CTA/SM, direct split-bf16 ctx output)
    attn_mma<<<dim3(SEQ / 128, BATCH * NHEAD), 256, ATTN_SMEM>>>(qsp, ksp, vsp, cs);

    // 7: output projection
    gemm_mma<0><<<ggrid, 128, GEMM_SMEM>>>(cs, wto, bo, out, rope_start, 1.0f);
}

// round 15
// speedup vs baseline: 1.2103x; 1.2103x over previous
#include <cuda_runtime.h>
#include <cuda_bf16.h>
#include <math.h>
#include <stdint.h>

#define BATCH 4
#define SEQ   2048
#define DMODEL 1024
#define NHEAD 16
#define HDIM  64
#define MTOT  8192          // BATCH*SEQ
#define KSP   2048          // 2*DMODEL (hi|lo)

// ---------------- scratch (device globals) ----------------
__device__ __nv_bfloat16 g_xs[MTOT * KSP];                   // x split  [M][2048]
__device__ __nv_bfloat16 g_wtq[DMODEL * KSP];                // W^T split [N][2048]
__device__ __nv_bfloat16 g_wtk[DMODEL * KSP];
__device__ __nv_bfloat16 g_wtv[DMODEL * KSP];
__device__ __nv_bfloat16 g_wto[DMODEL * KSP];
__device__ __nv_bfloat16 g_qsp[BATCH * NHEAD * SEQ * 2 * HDIM]; // [B,H,S,128] hi|lo
__device__ __nv_bfloat16 g_ksp[BATCH * NHEAD * SEQ * 2 * HDIM];
__device__ __nv_bfloat16 g_vsp[BATCH * NHEAD * SEQ * 2 * HDIM];
__device__ __nv_bfloat16 g_cs[MTOT * KSP];                   // ctx split [M][2048]

// ---------------- helpers ----------------
__device__ __forceinline__ uint32_t smem_u32(const void* p) {
    return (uint32_t)__cvta_generic_to_shared(p);
}
__device__ __forceinline__ void cp16(uint32_t s, const void* g) {
    asm volatile("cp.async.cg.shared.global [%0], [%1], 16;" :: "r"(s), "l"(g));
}
__device__ __forceinline__ void cp_commit() {
    asm volatile("cp.async.commit_group;" ::: "memory");
}
__device__ __forceinline__ void cp_wait1() {
    asm volatile("cp.async.wait_group 1;" ::: "memory");
}
__device__ __forceinline__ void cp_wait0() {
    asm volatile("cp.async.wait_group 0;" ::: "memory");
}
__device__ __forceinline__ void ldsm_x4(uint32_t& r0, uint32_t& r1, uint32_t& r2, uint32_t& r3, uint32_t a) {
    asm volatile("ldmatrix.sync.aligned.m8n8.x4.shared.b16 {%0,%1,%2,%3},[%4];"
                 : "=r"(r0), "=r"(r1), "=r"(r2), "=r"(r3) : "r"(a));
}
__device__ __forceinline__ void ldsm_x4t(uint32_t& r0, uint32_t& r1, uint32_t& r2, uint32_t& r3, uint32_t a) {
    asm volatile("ldmatrix.sync.aligned.m8n8.x4.trans.shared.b16 {%0,%1,%2,%3},[%4];"
                 : "=r"(r0), "=r"(r1), "=r"(r2), "=r"(r3) : "r"(a));
}
__device__ __forceinline__ void mma16816(float* c, const uint32_t* a, const uint32_t* b) {
    asm volatile(
        "mma.sync.aligned.m16n8k16.row.col.f32.bf16.bf16.f32 "
        "{%0,%1,%2,%3},{%4,%5,%6,%7},{%8,%9},{%0,%1,%2,%3};"
        : "+f"(c[0]), "+f"(c[1]), "+f"(c[2]), "+f"(c[3])
        : "r"(a[0]), "r"(a[1]), "r"(a[2]), "r"(a[3]), "r"(b[0]), "r"(b[1]));
}
__device__ __forceinline__ void pack_pair(float x0, float x1, uint32_t& hi, uint32_t& lo) {
    uint32_t h;
    asm("cvt.rn.bf16x2.f32 %0, %1, %2;" : "=r"(h) : "f"(x1), "f"(x0));
    __nv_bfloat162 h2 = *reinterpret_cast<__nv_bfloat162*>(&h);
    float r0 = x0 - __bfloat162float(h2.x);
    float r1 = x1 - __bfloat162float(h2.y);
    uint32_t l;
    asm("cvt.rn.bf16x2.f32 %0, %1, %2;" : "=r"(l) : "f"(r1), "f"(r0));
    hi = h; lo = l;
}

// ---------------- split: fp32 [M][1024] -> bf16 [M][2048] hi|lo ----------------
__global__ __launch_bounds__(256)
void split_kernel(const float* __restrict__ in, __nv_bfloat16* __restrict__ out)
{
    int i = blockIdx.x * 256 + threadIdx.x;
    float4 x = reinterpret_cast<const float4*>(in)[i];
    int r = i >> 8;
    int c = (i & 255) * 4;
    __nv_bfloat162 h0 = __floats2bfloat162_rn(x.x, x.y);
    __nv_bfloat162 h1 = __floats2bfloat162_rn(x.z, x.w);
    __nv_bfloat162 l0 = __floats2bfloat162_rn(x.x - __bfloat162float(h0.x), x.y - __bfloat162float(h0.y));
    __nv_bfloat162 l1 = __floats2bfloat162_rn(x.z - __bfloat162float(h1.x), x.w - __bfloat162float(h1.y));
    __nv_bfloat162* oh = reinterpret_cast<__nv_bfloat162*>(&out[(long)r * KSP + c]);
    oh[0] = h0; oh[1] = h1;
    __nv_bfloat162* ol = reinterpret_cast<__nv_bfloat162*>(&out[(long)r * KSP + 1024 + c]);
    ol[0] = l0; ol[1] = l1;
}

// ---------------- fused weight split+transpose (4 weights, blockIdx.z) ----------------
__global__ void wsplit_kernel(const float* __restrict__ W0, const float* __restrict__ W1,
                              const float* __restrict__ W2, const float* __restrict__ W3,
                              __nv_bfloat16* __restrict__ T0, __nv_bfloat16* __restrict__ T1,
                              __nv_bfloat16* __restrict__ T2, __nv_bfloat16* __restrict__ T3)
{
    const float* W = (blockIdx.z == 0) ? W0 : (blockIdx.z == 1) ? W1 : (blockIdx.z == 2) ? W2 : W3;
    __nv_bfloat16* Wt = (blockIdx.z == 0) ? T0 : (blockIdx.z == 1) ? T1 : (blockIdx.z == 2) ? T2 : T3;

    __shared__ float tile[32][33];
    int n0 = blockIdx.x * 32, k0 = blockIdx.y * 32;
    int tx = threadIdx.x, ty = threadIdx.y;   // 32 x 8
#pragma unroll
    for (int j = 0; j < 4; j++)
        tile[ty + 8 * j][tx] = W[(long)(k0 + ty + 8 * j) * DMODEL + n0 + tx];
    __syncthreads();
#pragma unroll
    for (int j = 0; j < 4; j++) {
        int n = n0 + ty + 8 * j;
        int k = k0 + tx;
        float v = tile[tx][ty + 8 * j];
        __nv_bfloat16 h = __float2bfloat16(v);
        Wt[(long)n * KSP + k] = h;
        Wt[(long)n * KSP + 1024 + k] = __float2bfloat16(v - __bfloat162float(h));
    }
}

// ---------------- split-bf16 tensor-core GEMM: grouped-pass @ 2 CTA/SM ----------------
// Per step: load {Ahi, Alo, Bhi, Blo} for one 32-wide k-chunk (40KB stage, 2-stage ring),
// run 3 passes (ah*bh, al*bh, ah*bl) = 96 MMAs/warp per sync. 32 steps.
// ah/bh fragments register-reused; al/bl loaded sequentially (caps live frags ~40 regs).
// OUT_MODE 0: plain fp32 [M][N]; 2: heads bf16-split; 3: heads + rope + scale
#define NSTEP 32
#define GPAD  40
#define TILE_ELEMS (128 * GPAD)             // 5120
#define STAGE_ELEMS (4 * TILE_ELEMS)        // 20480
#define GEMM_SMEM (2 * STAGE_ELEMS * 2)     // 81920 bytes -> 2 CTA/SM

template <int OUT_MODE>
__global__ __launch_bounds__(256, 2)
void gemm_mma(const __nv_bfloat16* __restrict__ A,
              const __nv_bfloat16* __restrict__ Bt,
              const float* __restrict__ bias,
              void* __restrict__ Cout,
              const int* __restrict__ start_p,
              float scale)
{
    extern __shared__ __align__(16) char smem_raw[];
    __nv_bfloat16* smem = reinterpret_cast<__nv_bfloat16*>(smem_raw);

    const int tid = threadIdx.x;
    const int lane = tid & 31;
    const int wid = tid >> 5;
    const int warp_m = wid & 1;        // 2 warps in M
    const int warp_n = wid >> 1;       // 4 warps in N
    const int m0 = blockIdx.y * 128;
    const int n0 = blockIdx.x * 128;

    float acc[4][4][4];
#pragma unroll
    for (int i = 0; i < 4; i++)
#pragma unroll
        for (int j = 0; j < 4; j++)
#pragma unroll
            for (int q = 0; q < 4; q++) acc[i][j][q] = 0.f;

    // loader: 512 (tile,row) units, 2/thread, 4 cp16 each (32 cols)
    auto issue = [&](int st, int step) {
        const int k0 = step << 5;
        __nv_bfloat16* base = smem + st * STAGE_ELEMS;
#pragma unroll
        for (int u = 0; u < 2; u++) {
            const int unit = tid + 256 * u;          // 0..511
            const int tile = unit >> 7;              // 0:Ahi 1:Alo 2:Bhi 3:Blo
            const int row  = unit & 127;
            const __nv_bfloat16* g;
            if (tile == 0)      g = &A [(long)(m0 + row) * KSP + k0];
            else if (tile == 1) g = &A [(long)(m0 + row) * KSP + 1024 + k0];
            else if (tile == 2) g = &Bt[(long)(n0 + row) * KSP + k0];
            else                g = &Bt[(long)(n0 + row) * KSP + 1024 + k0];
            const uint32_t s = smem_u32(base + tile * TILE_ELEMS + row * GPAD);
#pragma unroll
            for (int c = 0; c < 4; c++)
                cp16(s + c * 16, g + c * 8);
        }
    };

    issue(0, 0); cp_commit();

    const int mrow  = warp_m * 64 + (lane & 15);
    const int kfa   = (lane >> 4) << 3;
    const int nfrag = warp_n * 32 + ((lane >> 4) << 3) + (lane & 7);
    const int kfb   = ((lane >> 3) & 1) << 3;

    for (int step = 0; step < NSTEP; step++) {
        cp_wait0();
        __syncthreads();
        // prefetch next chunk into the OTHER buffer (no conflict with current reads)
        if (step + 1 < NSTEP) { issue((step + 1) & 1, step + 1); cp_commit(); }

        const __nv_bfloat16* S = smem + (step & 1) * STAGE_ELEMS;
        const __nv_bfloat16* Ahi = S;
        const __nv_bfloat16* Alo = S + TILE_ELEMS;
        const __nv_bfloat16* Bhi = S + 2 * TILE_ELEMS;
        const __nv_bfloat16* Blo = S + 3 * TILE_ELEMS;

#pragma unroll
        for (int kk = 0; kk < 32; kk += 16) {
            // pass 1: ah * bh  (ah, bh stay live for passes 2-3)
            uint32_t ah[4][4];
#pragma unroll
            for (int mt = 0; mt < 4; mt++)
                ldsm_x4(ah[mt][0], ah[mt][1], ah[mt][2], ah[mt][3],
                        smem_u32(&Ahi[(mrow + mt * 16) * GPAD + kk + kfa]));
            uint32_t bh[4][2];
#pragma unroll
            for (int bt = 0; bt < 2; bt++) {
                uint32_t r0, r1, r2, r3;
                ldsm_x4(r0, r1, r2, r3,
                        smem_u32(&Bhi[(nfrag + bt * 16) * GPAD + kk + kfb]));
                bh[2 * bt][0] = r0; bh[2 * bt][1] = r1;
                bh[2 * bt + 1][0] = r2; bh[2 * bt + 1][1] = r3;
            }
#pragma unroll
            for (int mt = 0; mt < 4; mt++)
#pragma unroll
                for (int nt = 0; nt < 4; nt++)
                    mma16816(acc[mt][nt], ah[mt], bh[nt]);

            // pass 2: al * bh
            {
                uint32_t al[4][4];
#pragma unroll
                for (int mt = 0; mt < 4; mt++)
                    ldsm_x4(al[mt][0], al[mt][1], al[mt][2], al[mt][3],
                            smem_u32(&Alo[(mrow + mt * 16) * GPAD + kk + kfa]));
#pragma unroll
                for (int mt = 0; mt < 4; mt++)
#pragma unroll
                    for (int nt = 0; nt < 4; nt++)
                        mma16816(acc[mt][nt], al[mt], bh[nt]);
            }

            // pass 3: ah * bl
            {
                uint32_t bl[4][2];
#pragma unroll
                for (int bt = 0; bt < 2; bt++) {
                    uint32_t r0, r1, r2, r3;
                    ldsm_x4(r0, r1, r2, r3,
                            smem_u32(&Blo[(nfrag + bt * 16) * GPAD + kk + kfb]));
                    bl[2 * bt][0] = r0; bl[2 * bt][1] = r1;
                    bl[2 * bt + 1][0] = r2; bl[2 * bt + 1][1] = r3;
                }
#pragma unroll
                for (int mt = 0; mt < 4; mt++)
#pragma unroll
                    for (int nt = 0; nt < 4; nt++)
                        mma16816(acc[mt][nt], ah[mt], bl[nt]);
            }
        }
    }

    // ---------------- epilogue ----------------
    const int r_m = warp_m * 64 + (lane >> 2);
    const int c_n = warp_n * 32 + 2 * (lane & 3);
    int start = 0;
    if (OUT_MODE == 3) start = *start_p;

#pragma unroll
    for (int mt = 0; mt < 4; mt++) {
#pragma unroll
        for (int nt = 0; nt < 4; nt++) {
            const int mg = m0 + r_m + mt * 16;
            const int ng = n0 + c_n + nt * 8;
            const float b0v = bias[ng], b1v = bias[ng + 1];
            float x0 = acc[mt][nt][0] + b0v, x1 = acc[mt][nt][1] + b1v;
            float y0 = acc[mt][nt][2] + b0v, y1 = acc[mt][nt][3] + b1v;

            if (OUT_MODE == 0) {
                float* outp = (float*)Cout;
                *(float2*)&outp[(long)mg * DMODEL + ng] = make_float2(x0, x1);
                *(float2*)&outp[(long)(mg + 8) * DMODEL + ng] = make_float2(y0, y1);
            } else {
                const int b = mg >> 11, s = mg & (SEQ - 1);
                const int h = ng >> 6, d = ng & (HDIM - 1);
                const long rowb = ((long)(b * NHEAD + h) * SEQ + s) * 128;
                __nv_bfloat16* outp = (__nv_bfloat16*)Cout;
#pragma unroll
                for (int rr = 0; rr < 2; rr++) {
                    float v0 = rr ? y0 : x0;
                    float v1 = rr ? y1 : x1;
                    int ss = s + rr * 8;
                    if (OUT_MODE == 3 && ss >= start) {
                        float pos = (float)(ss - start);
                        float invf = __expf(-(float)(d >> 1) * 0.28782313662425572f);
                        float sn, cs;
                        sincosf(pos * invf, &sn, &cs);
                        float t0 = v0 * cs - v1 * sn;
                        float t1 = v1 * cs + v0 * sn;
                        v0 = t0; v1 = t1;
                    }
                    v0 *= scale; v1 *= scale;
                    uint32_t hi, lo;
                    pack_pair(v0, v1, hi, lo);
                    long ro = rowb + (long)rr * 8 * 128;
                    *(uint32_t*)&outp[ro + d] = hi;
                    *(uint32_t*)&outp[ro + 64 + d] = lo;
                }
            }
        }
    }
}

// ---------------- flash attention (split-bf16 mma, cp.async 2-stage, 2 CTA/SM) ----------------
// [byte-identical to round 10 — validated at 1304.6 µs]
#define APAD 136
#define ATTN_STAGES 2
#define ATTN_SMEM (ATTN_STAGES * 64 * APAD * 2 * 2)

__global__ __launch_bounds__(256, 2)
void attn_mma(const __nv_bfloat16* __restrict__ qs,
              const __nv_bfloat16* __restrict__ ks,
              const __nv_bfloat16* __restrict__ vs,
              __nv_bfloat16* __restrict__ cs)
{
    extern __shared__ __align__(16) char smem_raw[];
    __nv_bfloat16* sK = reinterpret_cast<__nv_bfloat16*>(smem_raw);   // [2][64][136]
    __nv_bfloat16* sV = sK + ATTN_STAGES * 64 * APAD;                 // [2][64][136]

    const int tid = threadIdx.x;
    const int lane = tid & 31;
    const int wid = tid >> 5;
    const int qb = blockIdx.x;
    const int bh = blockIdx.y;
    const long hbase = (long)bh * SEQ * 128;

    {
        const __nv_bfloat16* qg = qs + hbase + (long)qb * 128 * 128;
        const int r = tid >> 1;
        const int c = (tid & 1) * 64;
#pragma unroll
        for (int i = 0; i < 8; i++)
            *(uint4*)&sK[r * APAD + c + i * 8] = *(const uint4*)&qg[(long)r * 128 + c + i * 8];
    }
    __syncthreads();
    uint32_t qhi[4][4], qlo[4][4];
    {
        const int mrow = wid * 16 + (lane & 15);
        const int kadd = (lane >> 4) << 3;
#pragma unroll
        for (int kc = 0; kc < 4; kc++) {
            ldsm_x4(qhi[kc][0], qhi[kc][1], qhi[kc][2], qhi[kc][3],
                    smem_u32(&sK[mrow * APAD + kc * 16 + kadd]));
            ldsm_x4(qlo[kc][0], qlo[kc][1], qlo[kc][2], qlo[kc][3],
                    smem_u32(&sK[mrow * APAD + 64 + kc * 16 + kadd]));
        }
    }
    __syncthreads();

    const int ldrow  = tid >> 4;
    const int ldc16  = tid & 15;
    auto issue = [&](int st, int kt) {
        const __nv_bfloat16* kg = ks + hbase + (long)kt * 64 * 128;
        const __nv_bfloat16* vg = vs + hbase + (long)kt * 64 * 128;
        __nv_bfloat16* sKs = sK + st * 64 * APAD;
        __nv_bfloat16* sVs = sV + st * 64 * APAD;
#pragma unroll
        for (int i = 0; i < 4; i++) {
            const int r = ldrow + 16 * i;
            cp16(smem_u32(&sKs[r * APAD + ldc16 * 8]), &kg[(long)r * 128 + ldc16 * 8]);
            cp16(smem_u32(&sVs[r * APAD + ldc16 * 8]), &vg[(long)r * 128 + ldc16 * 8]);
        }
    };

    float O[8][4];
#pragma unroll
    for (int i = 0; i < 8; i++)
#pragma unroll
        for (int j = 0; j < 4; j++) O[i][j] = 0.f;
    float m0 = -1e30f, m1 = -1e30f, l0 = 0.f, l1 = 0.f;

    issue(0, 0); cp_commit();
    issue(1, 1); cp_commit();

    const int NT = SEQ / 64;
    for (int kt = 0; kt < NT; kt++) {
        if (kt >= NT - 1) cp_wait0(); else cp_wait1();
        __syncthreads();

        const int st = kt & 1;
        const __nv_bfloat16* Kst = sK + st * 64 * APAD;
        const __nv_bfloat16* Vst = sV + st * 64 * APAD;

        float S[8][4];
#pragma unroll
        for (int i = 0; i < 8; i++)
#pragma unroll
            for (int j = 0; j < 4; j++) S[i][j] = 0.f;

#pragma unroll
        for (int kc = 0; kc < 4; kc++) {
            uint32_t b4[4][4];
#pragma unroll
            for (int bt = 0; bt < 4; bt++) {
                int n = bt * 16 + ((lane >> 4) << 3) + (lane & 7);
                int kcol = kc * 16 + (((lane >> 3) & 1) << 3);
                ldsm_x4(b4[bt][0], b4[bt][1], b4[bt][2], b4[bt][3],
                        smem_u32(&Kst[n * APAD + kcol]));
            }
#pragma unroll
            for (int bt = 0; bt < 4; bt++) {
                mma16816(S[2 * bt],     qhi[kc], &b4[bt][0]);
                mma16816(S[2 * bt + 1], qhi[kc], &b4[bt][2]);
                mma16816(S[2 * bt],     qlo[kc], &b4[bt][0]);
                mma16816(S[2 * bt + 1], qlo[kc], &b4[bt][2]);
            }
        }
#pragma unroll
        for (int kc = 0; kc < 4; kc++) {
            uint32_t b4[4][4];
#pragma unroll
            for (int bt = 0; bt < 4; bt++) {
                int n = bt * 16 + ((lane >> 4) << 3) + (lane & 7);
                int kcol = 64 + kc * 16 + (((lane >> 3) & 1) << 3);
                ldsm_x4(b4[bt][0], b4[bt][1], b4[bt][2], b4[bt][3],
                        smem_u32(&Kst[n * APAD + kcol]));
            }
#pragma unroll
            for (int bt = 0; bt < 4; bt++) {
                mma16816(S[2 * bt],     qhi[kc], &b4[bt][0]);
                mma16816(S[2 * bt + 1], qhi[kc], &b4[bt][2]);
            }
        }

        float tmax0 = -1e30f, tmax1 = -1e30f;
#pragma unroll
        for (int nt = 0; nt < 8; nt++) {
            tmax0 = fmaxf(tmax0, fmaxf(S[nt][0], S[nt][1]));
            tmax1 = fmaxf(tmax1, fmaxf(S[nt][2], S[nt][3]));
        }
        tmax0 = fmaxf(tmax0, __shfl_xor_sync(0xffffffffu, tmax0, 1));
        tmax0 = fmaxf(tmax0, __shfl_xor_sync(0xffffffffu, tmax0, 2));
        tmax1 = fmaxf(tmax1, __shfl_xor_sync(0xffffffffu, tmax1, 1));
        tmax1 = fmaxf(tmax1, __shfl_xor_sync(0xffffffffu, tmax1, 2));
        const float mn0 = fmaxf(m0, tmax0);
        const float mn1 = fmaxf(m1, tmax1);
        const float corr0 = __expf(m0 - mn0);
        const float corr1 = __expf(m1 - mn1);
        m0 = mn0; m1 = mn1;
#pragma unroll
        for (int nt = 0; nt < 8; nt++) {
            O[nt][0] *= corr0; O[nt][1] *= corr0;
            O[nt][2] *= corr1; O[nt][3] *= corr1;
        }

        float sum0 = 0.f, sum1 = 0.f;
        uint32_t phi[4][4], plo[4][4];
#pragma unroll
        for (int bt = 0; bt < 4; bt++) {
            float p00 = __expf(S[2 * bt][0] - mn0), p01 = __expf(S[2 * bt][1] - mn0);
            float p02 = __expf(S[2 * bt][2] - mn1), p03 = __expf(S[2 * bt][3] - mn1);
            float p10 = __expf(S[2 * bt + 1][0] - mn0), p11 = __expf(S[2 * bt + 1][1] - mn0);
            float p12 = __expf(S[2 * bt + 1][2] - mn1), p13 = __expf(S[2 * bt + 1][3] - mn1);
            sum0 += p00 + p01 + p10 + p11;
            sum1 += p02 + p03 + p12 + p13;
            pack_pair(p00, p01, phi[bt][0], plo[bt][0]);
            pack_pair(p02, p03, phi[bt][1], plo[bt][1]);
            pack_pair(p10, p11, phi[bt][2], plo[bt][2]);
            pack_pair(p12, p13, phi[bt][3], plo[bt][3]);
        }
        sum0 += __shfl_xor_sync(0xffffffffu, sum0, 1);
        sum0 += __shfl_xor_sync(0xffffffffu, sum0, 2);
        sum1 += __shfl_xor_sync(0xffffffffu, sum1, 1);
        sum1 += __shfl_xor_sync(0xffffffffu, sum1, 2);
        l0 = l0 * corr0 + sum0;
        l1 = l1 * corr1 + sum1;

#pragma unroll
        for (int kc = 0; kc < 4; kc++) {
            uint32_t vb[4][4];
#pragma unroll
            for (int ntp = 0; ntp < 4; ntp++) {
                int key = kc * 16 + ((lane >> 3) & 1) * 8 + (lane & 7);
                int col = ntp * 16 + ((lane >> 4) << 3);
                ldsm_x4t(vb[ntp][0], vb[ntp][1], vb[ntp][2], vb[ntp][3],
                         smem_u32(&Vst[key * APAD + col]));
            }
#pragma unroll
            for (int ntp = 0; ntp < 4; ntp++) {
                mma16816(O[2 * ntp],     phi[kc], &vb[ntp][0]);
                mma16816(O[2 * ntp + 1], phi[kc], &vb[ntp][2]);
                mma16816(O[2 * ntp],     plo[kc], &vb[ntp][0]);
                mma16816(O[2 * ntp + 1], plo[kc], &vb[ntp][2]);
            }
        }
#pragma unroll
        for (int kc = 0; kc < 4; kc++) {
            uint32_t vb[4][4];
#pragma unroll
            for (int ntp = 0; ntp < 4; ntp++) {
                int key = kc * 16 + ((lane >> 3) & 1) * 8 + (lane & 7);
                int col = 64 + ntp * 16 + ((lane >> 4) << 3);
                ldsm_x4t(vb[ntp][0], vb[ntp][1], vb[ntp][2], vb[ntp][3],
                         smem_u32(&Vst[key * APAD + col]));
            }
#pragma unroll
            for (int ntp = 0; ntp < 4; ntp++) {
                mma16816(O[2 * ntp],     phi[kc], &vb[ntp][0]);
                mma16816(O[2 * ntp + 1], phi[kc], &vb[ntp][2]);
            }
        }

        __syncthreads();
        if (kt + 2 < NT) { issue(st, kt + 2); cp_commit(); }
    }

    const float inv0 = 1.f / l0;
    const float inv1 = 1.f / l1;
    const int b = bh >> 4, h = bh & 15;
    const int s0 = qb * 128 + wid * 16 + (lane >> 2);
    const long row0 = (long)(b * SEQ + s0) * KSP;
    const long row1 = row0 + (long)8 * KSP;
#pragma unroll
    for (int nt = 0; nt < 8; nt++) {
        int c = h * HDIM + nt * 8 + 2 * (lane & 3);
        uint32_t hi, lo;
        pack_pair(O[nt][0] * inv0, O[nt][1] * inv0, hi, lo);
        *(uint32_t*)&cs[row0 + c] = hi;
        *(uint32_t*)&cs[row0 + 1024 + c] = lo;
        pack_pair(O[nt][2] * inv1, O[nt][3] * inv1, hi, lo);
        *(uint32_t*)&cs[row1 + c] = hi;
        *(uint32_t*)&cs[row1 + 1024 + c] = lo;
    }
}

// ---------------- launch ----------------
extern "C" void kernel_launch(void* const* d_in, const int* in_sizes, int n_in,
                              void* d_out, int out_size)
{
    const float* x  = (const float*)d_in[0];
    const float* Wq = (const float*)d_in[1];
    const float* bq = (const float*)d_in[2];
    const float* Wk = (const float*)d_in[3];
    const float* bk = (const float*)d_in[4];
    const float* Wv = (const float*)d_in[5];
    const float* bv = (const float*)d_in[6];
    const float* Wo = (const float*)d_in[7];
    const float* bo = (const float*)d_in[8];
    const int* rope_start = (const int*)d_in[9];
    float* out = (float*)d_out;

    __nv_bfloat16 *xs, *wtq, *wtk, *wtv, *wto, *qsp, *ksp, *vsp, *cs;
    cudaGetSymbolAddress((void**)&xs,  g_xs);
    cudaGetSymbolAddress((void**)&wtq, g_wtq);
    cudaGetSymbolAddress((void**)&wtk, g_wtk);
    cudaGetSymbolAddress((void**)&wtv, g_wtv);
    cudaGetSymbolAddress((void**)&wto, g_wto);
    cudaGetSymbolAddress((void**)&qsp, g_qsp);
    cudaGetSymbolAddress((void**)&ksp, g_ksp);
    cudaGetSymbolAddress((void**)&vsp, g_vsp);
    cudaGetSymbolAddress((void**)&cs,  g_cs);

    static bool attr_done = false;
    if (!attr_done) {
        cudaFuncSetAttribute(gemm_mma<0>, cudaFuncAttributeMaxDynamicSharedMemorySize, GEMM_SMEM);
        cudaFuncSetAttribute(gemm_mma<2>, cudaFuncAttributeMaxDynamicSharedMemorySize, GEMM_SMEM);
        cudaFuncSetAttribute(gemm_mma<3>, cudaFuncAttributeMaxDynamicSharedMemorySize, GEMM_SMEM);
        cudaFuncSetAttribute(attn_mma,    cudaFuncAttributeMaxDynamicSharedMemorySize, ATTN_SMEM);
        attr_done = true;
    }

    // 1: input split
    split_kernel<<<MTOT, 256>>>(x, xs);
    // 2: fused weight splits
    dim3 wgrid(32, 32, 4), wblock(32, 8);
    wsplit_kernel<<<wgrid, wblock>>>(Wq, Wk, Wv, Wo, wtq, wtk, wtv, wto);

    // 3-5: projections (grouped-pass GEMM @ 2 CTA/SM)
    dim3 ggrid(DMODEL / 128, MTOT / 128);     // (8, 64)
    gemm_mma<3><<<ggrid, 256, GEMM_SMEM>>>(xs, wtq, bq, qsp, rope_start, 0.125f);
    gemm_mma<3><<<ggrid, 256, GEMM_SMEM>>>(xs, wtk, bk, ksp, rope_start, 1.0f);
    gemm_mma<2><<<ggrid, 256, GEMM_SMEM>>>(xs, wtv, bv, vsp, rope_start, 1.0f);

    // 6: attention (2-stage, 2 CTA/SM, direct split-bf16 ctx output)
    attn_mma<<<dim3(SEQ / 128, BATCH * NHEAD), 256, ATTN_SMEM>>>(qsp, ksp, vsp, cs);

    // 7: output projection
    gemm_mma<0><<<ggrid, 256, GEMM_SMEM>>>(cs, wto, bo, out, rope_start, 1.0f);
}

// round 16
// speedup vs baseline: 1.4243x; 1.1768x over previous
#include <cuda_runtime.h>
#include <cuda_bf16.h>
#include <math.h>
#include <stdint.h>

#define BATCH 4
#define SEQ   2048
#define DMODEL 1024
#define NHEAD 16
#define HDIM  64
#define MTOT  8192          // BATCH*SEQ
#define KSP   2048          // 2*DMODEL (hi|lo)

// ---------------- scratch (device globals) ----------------
__device__ __nv_bfloat16 g_xs[MTOT * KSP];                   // x split  [M][2048]
__device__ __nv_bfloat16 g_wtq[DMODEL * KSP];                // W^T split [N][2048]
__device__ __nv_bfloat16 g_wtk[DMODEL * KSP];
__device__ __nv_bfloat16 g_wtv[DMODEL * KSP];
__device__ __nv_bfloat16 g_wto[DMODEL * KSP];
__device__ __nv_bfloat16 g_qsp[BATCH * NHEAD * SEQ * 2 * HDIM]; // [B,H,S,128] hi|lo
__device__ __nv_bfloat16 g_ksp[BATCH * NHEAD * SEQ * 2 * HDIM];
__device__ __nv_bfloat16 g_vsp[BATCH * NHEAD * SEQ * 2 * HDIM];
__device__ __nv_bfloat16 g_cs[MTOT * KSP];                   // ctx split [M][2048]

// ---------------- helpers ----------------
__device__ __forceinline__ uint32_t smem_u32(const void* p) {
    return (uint32_t)__cvta_generic_to_shared(p);
}
__device__ __forceinline__ void cp16(uint32_t s, const void* g) {
    asm volatile("cp.async.cg.shared.global [%0], [%1], 16;" :: "r"(s), "l"(g));
}
__device__ __forceinline__ void cp_commit() {
    asm volatile("cp.async.commit_group;" ::: "memory");
}
__device__ __forceinline__ void cp_wait1() {
    asm volatile("cp.async.wait_group 1;" ::: "memory");
}
__device__ __forceinline__ void cp_wait0() {
    asm volatile("cp.async.wait_group 0;" ::: "memory");
}
__device__ __forceinline__ void ldsm_x4(uint32_t& r0, uint32_t& r1, uint32_t& r2, uint32_t& r3, uint32_t a) {
    asm volatile("ldmatrix.sync.aligned.m8n8.x4.shared.b16 {%0,%1,%2,%3},[%4];"
                 : "=r"(r0), "=r"(r1), "=r"(r2), "=r"(r3) : "r"(a));
}
__device__ __forceinline__ void ldsm_x4t(uint32_t& r0, uint32_t& r1, uint32_t& r2, uint32_t& r3, uint32_t a) {
    asm volatile("ldmatrix.sync.aligned.m8n8.x4.trans.shared.b16 {%0,%1,%2,%3},[%4];"
                 : "=r"(r0), "=r"(r1), "=r"(r2), "=r"(r3) : "r"(a));
}
__device__ __forceinline__ void mma16816(float* c, const uint32_t* a, const uint32_t* b) {
    asm volatile(
        "mma.sync.aligned.m16n8k16.row.col.f32.bf16.bf16.f32 "
        "{%0,%1,%2,%3},{%4,%5,%6,%7},{%8,%9},{%0,%1,%2,%3};"
        : "+f"(c[0]), "+f"(c[1]), "+f"(c[2]), "+f"(c[3])
        : "r"(a[0]), "r"(a[1]), "r"(a[2]), "r"(a[3]), "r"(b[0]), "r"(b[1]));
}
__device__ __forceinline__ void pack_pair(float x0, float x1, uint32_t& hi, uint32_t& lo) {
    uint32_t h;
    asm("cvt.rn.bf16x2.f32 %0, %1, %2;" : "=r"(h) : "f"(x1), "f"(x0));
    __nv_bfloat162 h2 = *reinterpret_cast<__nv_bfloat162*>(&h);
    float r0 = x0 - __bfloat162float(h2.x);
    float r1 = x1 - __bfloat162float(h2.y);
    uint32_t l;
    asm("cvt.rn.bf16x2.f32 %0, %1, %2;" : "=r"(l) : "f"(r1), "f"(r0));
    hi = h; lo = l;
}

// ---------------- split: fp32 [M][1024] -> bf16 [M][2048] hi|lo ----------------
__global__ __launch_bounds__(256)
void split_kernel(const float* __restrict__ in, __nv_bfloat16* __restrict__ out)
{
    int i = blockIdx.x * 256 + threadIdx.x;
    float4 x = reinterpret_cast<const float4*>(in)[i];
    int r = i >> 8;
    int c = (i & 255) * 4;
    __nv_bfloat162 h0 = __floats2bfloat162_rn(x.x, x.y);
    __nv_bfloat162 h1 = __floats2bfloat162_rn(x.z, x.w);
    __nv_bfloat162 l0 = __floats2bfloat162_rn(x.x - __bfloat162float(h0.x), x.y - __bfloat162float(h0.y));
    __nv_bfloat162 l1 = __floats2bfloat162_rn(x.z - __bfloat162float(h1.x), x.w - __bfloat162float(h1.y));
    __nv_bfloat162* oh = reinterpret_cast<__nv_bfloat162*>(&out[(long)r * KSP + c]);
    oh[0] = h0; oh[1] = h1;
    __nv_bfloat162* ol = reinterpret_cast<__nv_bfloat162*>(&out[(long)r * KSP + 1024 + c]);
    ol[0] = l0; ol[1] = l1;
}

// ---------------- fused weight split+transpose (4 weights, blockIdx.z) ----------------
__global__ void wsplit_kernel(const float* __restrict__ W0, const float* __restrict__ W1,
                              const float* __restrict__ W2, const float* __restrict__ W3,
                              __nv_bfloat16* __restrict__ T0, __nv_bfloat16* __restrict__ T1,
                              __nv_bfloat16* __restrict__ T2, __nv_bfloat16* __restrict__ T3)
{
    const float* W = (blockIdx.z == 0) ? W0 : (blockIdx.z == 1) ? W1 : (blockIdx.z == 2) ? W2 : W3;
    __nv_bfloat16* Wt = (blockIdx.z == 0) ? T0 : (blockIdx.z == 1) ? T1 : (blockIdx.z == 2) ? T2 : T3;

    __shared__ float tile[32][33];
    int n0 = blockIdx.x * 32, k0 = blockIdx.y * 32;
    int tx = threadIdx.x, ty = threadIdx.y;   // 32 x 8
#pragma unroll
    for (int j = 0; j < 4; j++)
        tile[ty + 8 * j][tx] = W[(long)(k0 + ty + 8 * j) * DMODEL + n0 + tx];
    __syncthreads();
#pragma unroll
    for (int j = 0; j < 4; j++) {
        int n = n0 + ty + 8 * j;
        int k = k0 + tx;
        float v = tile[tx][ty + 8 * j];
        __nv_bfloat16 h = __float2bfloat16(v);
        Wt[(long)n * KSP + k] = h;
        Wt[(long)n * KSP + 1024 + k] = __float2bfloat16(v - __bfloat162float(h));
    }
}

// ---------------- split-bf16 tensor-core GEMM (round-10 frozen: 3-stage, BK=64, 2 CTA/SM) ----------------
// OUT_MODE 0: plain fp32 [M][N]; 2: heads bf16-split; 3: heads + rope + scale
#define NSTEP 48
#define GPAD  72
#define GEMM_SMEM (3 * 128 * GPAD * 2 * 2)

template <int OUT_MODE>
__global__ __launch_bounds__(256, 2)
void gemm_mma(const __nv_bfloat16* __restrict__ A,
              const __nv_bfloat16* __restrict__ Bt,
              const float* __restrict__ bias,
              void* __restrict__ Cout,
              const int* __restrict__ start_p,
              float scale)
{
    extern __shared__ __align__(16) char smem_raw[];
    __nv_bfloat16* sA = reinterpret_cast<__nv_bfloat16*>(smem_raw);                // [3][128][72]
    __nv_bfloat16* sB = sA + 3 * 128 * GPAD;                                       // [3][128][72]

    const int tid = threadIdx.x;
    const int lane = tid & 31;
    const int wid = tid >> 5;
    const int warp_m = wid & 1;
    const int warp_n = wid >> 1;
    const int m0 = blockIdx.y * 128;
    const int n0 = blockIdx.x * 128;

    float acc[4][4][4];
#pragma unroll
    for (int i = 0; i < 4; i++)
#pragma unroll
        for (int j = 0; j < 4; j++)
#pragma unroll
            for (int q = 0; q < 4; q++) acc[i][j][q] = 0.f;

    const int ldrow = tid >> 3;   // 0..31
    const int ldc8  = tid & 7;    // chunk col (64 cols per stage)

    auto issue = [&](int st, int step) {
        const int seg = step >> 4;
        const int ks  = (step & 15) << 6;
        const int aoff = (seg == 1 ? 1024 : 0) + ks;
        const int boff = (seg == 2 ? 1024 : 0) + ks;
        __nv_bfloat16* sAs = sA + st * 128 * GPAD;
        __nv_bfloat16* sBs = sB + st * 128 * GPAD;
#pragma unroll
        for (int i = 0; i < 4; i++) {
            const int r = ldrow + 32 * i;
            cp16(smem_u32(&sAs[r * GPAD + ldc8 * 8]),
                 &A[(long)(m0 + r) * KSP + aoff + ldc8 * 8]);
            cp16(smem_u32(&sBs[r * GPAD + ldc8 * 8]),
                 &Bt[(long)(n0 + r) * KSP + boff + ldc8 * 8]);
        }
    };

    issue(0, 0); cp_commit();
    issue(1, 1); cp_commit();

    for (int step = 0; step < NSTEP; step++) {
        if (step == NSTEP - 1) cp_wait0(); else cp_wait1();
        __syncthreads();
        if (step + 2 < NSTEP) { issue((step + 2) % 3, step + 2); cp_commit(); }

        const int st = step % 3;
        const __nv_bfloat16* sAs = sA + st * 128 * GPAD;
        const __nv_bfloat16* sBs = sB + st * 128 * GPAD;

#pragma unroll
        for (int kk = 0; kk < 64; kk += 16) {
            uint32_t af[4][4];
            const int mrow = warp_m * 64 + (lane & 15);
            const int kcol = kk + ((lane >> 4) << 3);
#pragma unroll
            for (int mt = 0; mt < 4; mt++)
                ldsm_x4(af[mt][0], af[mt][1], af[mt][2], af[mt][3],
                        smem_u32(&sAs[(mrow + mt * 16) * GPAD + kcol]));
            uint32_t bfr[4][2];
#pragma unroll
            for (int bt = 0; bt < 2; bt++) {
                int n = warp_n * 32 + bt * 16 + ((lane >> 4) << 3) + (lane & 7);
                int kc2 = kk + (((lane >> 3) & 1) << 3);
                uint32_t r0, r1, r2, r3;
                ldsm_x4(r0, r1, r2, r3, smem_u32(&sBs[n * GPAD + kc2]));
                bfr[2 * bt][0] = r0; bfr[2 * bt][1] = r1;
                bfr[2 * bt + 1][0] = r2; bfr[2 * bt + 1][1] = r3;
            }
#pragma unroll
            for (int mt = 0; mt < 4; mt++)
#pragma unroll
                for (int nt = 0; nt < 4; nt++)
                    mma16816(acc[mt][nt], af[mt], bfr[nt]);
        }
    }

    // ---------------- epilogue ----------------
    const int r_m = warp_m * 64 + (lane >> 2);
    const int c_n = warp_n * 32 + 2 * (lane & 3);
    int start = 0;
    if (OUT_MODE == 3) start = *start_p;

#pragma unroll
    for (int mt = 0; mt < 4; mt++) {
#pragma unroll
        for (int nt = 0; nt < 4; nt++) {
            const int mg = m0 + r_m + mt * 16;
            const int ng = n0 + c_n + nt * 8;
            const float b0v = bias[ng], b1v = bias[ng + 1];
            float x0 = acc[mt][nt][0] + b0v, x1 = acc[mt][nt][1] + b1v;
            float y0 = acc[mt][nt][2] + b0v, y1 = acc[mt][nt][3] + b1v;

            if (OUT_MODE == 0) {
                float* outp = (float*)Cout;
                *(float2*)&outp[(long)mg * DMODEL + ng] = make_float2(x0, x1);
                *(float2*)&outp[(long)(mg + 8) * DMODEL + ng] = make_float2(y0, y1);
            } else {
                const int b = mg >> 11, s = mg & (SEQ - 1);
                const int h = ng >> 6, d = ng & (HDIM - 1);
                const long rowb = ((long)(b * NHEAD + h) * SEQ + s) * 128;
                __nv_bfloat16* outp = (__nv_bfloat16*)Cout;
#pragma unroll
                for (int rr = 0; rr < 2; rr++) {
                    float v0 = rr ? y0 : x0;
                    float v1 = rr ? y1 : x1;
                    int ss = s + rr * 8;
                    if (OUT_MODE == 3 && ss >= start) {
                        float pos = (float)(ss - start);
                        float invf = __expf(-(float)(d >> 1) * 0.28782313662425572f);
                        float sn, cs;
                        sincosf(pos * invf, &sn, &cs);
                        float t0 = v0 * cs - v1 * sn;
                        float t1 = v1 * cs + v0 * sn;
                        v0 = t0; v1 = t1;
                    }
                    v0 *= scale; v1 *= scale;
                    uint32_t hi, lo;
                    pack_pair(v0, v1, hi, lo);
                    long ro = rowb + (long)rr * 8 * 128;
                    *(uint32_t*)&outp[ro + d] = hi;
                    *(uint32_t*)&outp[ro + 64 + d] = lo;
                }
            }
        }
    }
}

// ---------------- flash attention: 3-stage ring + single sync + 2 CTA/SM ----------------
// grid (SEQ/128, B*H), 256 threads (8 warps, 16 q-rows each)
#define APAD 136
#define ATTN_STAGES 3
#define ATTN_SMEM (ATTN_STAGES * 64 * APAD * 2 * 2)   // 104448 bytes; 2 CTAs = 208896

__global__ __launch_bounds__(256, 2)
void attn_mma(const __nv_bfloat16* __restrict__ qs,
              const __nv_bfloat16* __restrict__ ks,
              const __nv_bfloat16* __restrict__ vs,
              __nv_bfloat16* __restrict__ cs)
{
    extern __shared__ __align__(16) char smem_raw[];
    __nv_bfloat16* sK = reinterpret_cast<__nv_bfloat16*>(smem_raw);   // [3][64][136]
    __nv_bfloat16* sV = sK + ATTN_STAGES * 64 * APAD;                 // [3][64][136]

    const int tid = threadIdx.x;
    const int lane = tid & 31;
    const int wid = tid >> 5;
    const int qb = blockIdx.x;
    const int bh = blockIdx.y;
    const long hbase = (long)bh * SEQ * 128;

    // stage Q (128x128) into sK rows 0..127 (spans stages 0-1)
    {
        const __nv_bfloat16* qg = qs + hbase + (long)qb * 128 * 128;
        const int r = tid >> 1;
        const int c = (tid & 1) * 64;
#pragma unroll
        for (int i = 0; i < 8; i++)
            *(uint4*)&sK[r * APAD + c + i * 8] = *(const uint4*)&qg[(long)r * 128 + c + i * 8];
    }
    __syncthreads();
    uint32_t qhi[4][4], qlo[4][4];
    {
        const int mrow = wid * 16 + (lane & 15);
        const int kadd = (lane >> 4) << 3;
#pragma unroll
        for (int kc = 0; kc < 4; kc++) {
            ldsm_x4(qhi[kc][0], qhi[kc][1], qhi[kc][2], qhi[kc][3],
                    smem_u32(&sK[mrow * APAD + kc * 16 + kadd]));
            ldsm_x4(qlo[kc][0], qlo[kc][1], qlo[kc][2], qlo[kc][3],
                    smem_u32(&sK[mrow * APAD + 64 + kc * 16 + kadd]));
        }
    }
    __syncthreads();

    const int ldrow  = tid >> 4;
    const int ldc16  = tid & 15;
    auto issue = [&](int st, int kt) {
        const __nv_bfloat16* kg = ks + hbase + (long)kt * 64 * 128;
        const __nv_bfloat16* vg = vs + hbase + (long)kt * 64 * 128;
        __nv_bfloat16* sKs = sK + st * 64 * APAD;
        __nv_bfloat16* sVs = sV + st * 64 * APAD;
#pragma unroll
        for (int i = 0; i < 4; i++) {
            const int r = ldrow + 16 * i;
            cp16(smem_u32(&sKs[r * APAD + ldc16 * 8]), &kg[(long)r * 128 + ldc16 * 8]);
            cp16(smem_u32(&sVs[r * APAD + ldc16 * 8]), &vg[(long)r * 128 + ldc16 * 8]);
        }
    };

    float O[8][4];
#pragma unroll
    for (int i = 0; i < 8; i++)
#pragma unroll
        for (int j = 0; j < 4; j++) O[i][j] = 0.f;
    float m0 = -1e30f, m1 = -1e30f, l0 = 0.f, l1 = 0.f;

    issue(0, 0); cp_commit();
    issue(1, 1); cp_commit();

    const int NT = SEQ / 64;
    for (int kt = 0; kt < NT; kt++) {
        if (kt == NT - 1) cp_wait0(); else cp_wait1();
        __syncthreads();
        // stage (kt+2)%3 was last read in iteration kt-1; the sync above makes refill safe
        if (kt + 2 < NT) { issue((kt + 2) % 3, kt + 2); cp_commit(); }

        const int st = kt % 3;
        const __nv_bfloat16* Kst = sK + st * 64 * APAD;
        const __nv_bfloat16* Vst = sV + st * 64 * APAD;

        float S[8][4];
#pragma unroll
        for (int i = 0; i < 8; i++)
#pragma unroll
            for (int j = 0; j < 4; j++) S[i][j] = 0.f;

#pragma unroll
        for (int kc = 0; kc < 4; kc++) {
            uint32_t b4[4][4];
#pragma unroll
            for (int bt = 0; bt < 4; bt++) {
                int n = bt * 16 + ((lane >> 4) << 3) + (lane & 7);
                int kcol = kc * 16 + (((lane >> 3) & 1) << 3);
                ldsm_x4(b4[bt][0], b4[bt][1], b4[bt][2], b4[bt][3],
                        smem_u32(&Kst[n * APAD + kcol]));
            }
#pragma unroll
            for (int bt = 0; bt < 4; bt++) {
                mma16816(S[2 * bt],     qhi[kc], &b4[bt][0]);
                mma16816(S[2 * bt + 1], qhi[kc], &b4[bt][2]);
                mma16816(S[2 * bt],     qlo[kc], &b4[bt][0]);
                mma16816(S[2 * bt + 1], qlo[kc], &b4[bt][2]);
            }
        }
#pragma unroll
        for (int kc = 0; kc < 4; kc++) {
            uint32_t b4[4][4];
#pragma unroll
            for (int bt = 0; bt < 4; bt++) {
                int n = bt * 16 + ((lane >> 4) << 3) + (lane & 7);
                int kcol = 64 + kc * 16 + (((lane >> 3) & 1) << 3);
                ldsm_x4(b4[bt][0], b4[bt][1], b4[bt][2], b4[bt][3],
                        smem_u32(&Kst[n * APAD + kcol]));
            }
#pragma unroll
            for (int bt = 0; bt < 4; bt++) {
                mma16816(S[2 * bt],     qhi[kc], &b4[bt][0]);
                mma16816(S[2 * bt + 1], qhi[kc], &b4[bt][2]);
            }
        }

        float tmax0 = -1e30f, tmax1 = -1e30f;
#pragma unroll
        for (int nt = 0; nt < 8; nt++) {
            tmax0 = fmaxf(tmax0, fmaxf(S[nt][0], S[nt][1]));
            tmax1 = fmaxf(tmax1, fmaxf(S[nt][2], S[nt][3]));
        }
        tmax0 = fmaxf(tmax0, __shfl_xor_sync(0xffffffffu, tmax0, 1));
        tmax0 = fmaxf(tmax0, __shfl_xor_sync(0xffffffffu, tmax0, 2));
        tmax1 = fmaxf(tmax1, __shfl_xor_sync(0xffffffffu, tmax1, 1));
        tmax1 = fmaxf(tmax1, __shfl_xor_sync(0xffffffffu, tmax1, 2));
        const float mn0 = fmaxf(m0, tmax0);
        const float mn1 = fmaxf(m1, tmax1);
        const float corr0 = __expf(m0 - mn0);
        const float corr1 = __expf(m1 - mn1);
        m0 = mn0; m1 = mn1;
#pragma unroll
        for (int nt = 0; nt < 8; nt++) {
            O[nt][0] *= corr0; O[nt][1] *= corr0;
            O[nt][2] *= corr1; O[nt][3] *= corr1;
        }

        float sum0 = 0.f, sum1 = 0.f;
        uint32_t phi[4][4], plo[4][4];
#pragma unroll
        for (int bt = 0; bt < 4; bt++) {
            float p00 = __expf(S[2 * bt][0] - mn0), p01 = __expf(S[2 * bt][1] - mn0);
            float p02 = __expf(S[2 * bt][2] - mn1), p03 = __expf(S[2 * bt][3] - mn1);
            float p10 = __expf(S[2 * bt + 1][0] - mn0), p11 = __expf(S[2 * bt + 1][1] - mn0);
            float p12 = __expf(S[2 * bt + 1][2] - mn1), p13 = __expf(S[2 * bt + 1][3] - mn1);
            sum0 += p00 + p01 + p10 + p11;
            sum1 += p02 + p03 + p12 + p13;
            pack_pair(p00, p01, phi[bt][0], plo[bt][0]);
            pack_pair(p02, p03, phi[bt][1], plo[bt][1]);
            pack_pair(p10, p11, phi[bt][2], plo[bt][2]);
            pack_pair(p12, p13, phi[bt][3], plo[bt][3]);
        }
        sum0 += __shfl_xor_sync(0xffffffffu, sum0, 1);
        sum0 += __shfl_xor_sync(0xffffffffu, sum0, 2);
        sum1 += __shfl_xor_sync(0xffffffffu, sum1, 1);
        sum1 += __shfl_xor_sync(0xffffffffu, sum1, 2);
        l0 = l0 * corr0 + sum0;
        l1 = l1 * corr1 + sum1;

#pragma unroll
        for (int kc = 0; kc < 4; kc++) {
            uint32_t vb[4][4];
#pragma unroll
            for (int ntp = 0; ntp < 4; ntp++) {
                int key = kc * 16 + ((lane >> 3) & 1) * 8 + (lane & 7);
                int col = ntp * 16 + ((lane >> 4) << 3);
                ldsm_x4t(vb[ntp][0], vb[ntp][1], vb[ntp][2], vb[ntp][3],
                         smem_u32(&Vst[key * APAD + col]));
            }
#pragma unroll
            for (int ntp = 0; ntp < 4; ntp++) {
                mma16816(O[2 * ntp],     phi[kc], &vb[ntp][0]);
                mma16816(O[2 * ntp + 1], phi[kc], &vb[ntp][2]);
                mma16816(O[2 * ntp],     plo[kc], &vb[ntp][0]);
                mma16816(O[2 * ntp + 1], plo[kc], &vb[ntp][2]);
            }
        }
#pragma unroll
        for (int kc = 0; kc < 4; kc++) {
            uint32_t vb[4][4];
#pragma unroll
            for (int ntp = 0; ntp < 4; ntp++) {
                int key = kc * 16 + ((lane >> 3) & 1) * 8 + (lane & 7);
                int col = 64 + ntp * 16 + ((lane >> 4) << 3);
                ldsm_x4t(vb[ntp][0], vb[ntp][1], vb[ntp][2], vb[ntp][3],
                         smem_u32(&Vst[key * APAD + col]));
            }
#pragma unroll
            for (int ntp = 0; ntp < 4; ntp++) {
                mma16816(O[2 * ntp],     phi[kc], &vb[ntp][0]);
                mma16816(O[2 * ntp + 1], phi[kc], &vb[ntp][2]);
            }
        }
    }

    const float inv0 = 1.f / l0;
    const float inv1 = 1.f / l1;
    const int b = bh >> 4, h = bh & 15;
    const int s0 = qb * 128 + wid * 16 + (lane >> 2);
    const long row0 = (long)(b * SEQ + s0) * KSP;
    const long row1 = row0 + (long)8 * KSP;
#pragma unroll
    for (int nt = 0; nt < 8; nt++) {
        int c = h * HDIM + nt * 8 + 2 * (lane & 3);
        uint32_t hi, lo;
        pack_pair(O[nt][0] * inv0, O[nt][1] * inv0, hi, lo);
        *(uint32_t*)&cs[row0 + c] = hi;
        *(uint32_t*)&cs[row0 + 1024 + c] = lo;
        pack_pair(O[nt][2] * inv1, O[nt][3] * inv1, hi, lo);
        *(uint32_t*)&cs[row1 + c] = hi;
        *(uint32_t*)&cs[row1 + 1024 + c] = lo;
    }
}

// ---------------- launch ----------------
extern "C" void kernel_launch(void* const* d_in, const int* in_sizes, int n_in,
                              void* d_out, int out_size)
{
    const float* x  = (const float*)d_in[0];
    const float* Wq = (const float*)d_in[1];
    const float* bq = (const float*)d_in[2];
    const float* Wk = (const float*)d_in[3];
    const float* bk = (const float*)d_in[4];
    const float* Wv = (const float*)d_in[5];
    const float* bv = (const float*)d_in[6];
    const float* Wo = (const float*)d_in[7];
    const float* bo = (const float*)d_in[8];
    const int* rope_start = (const int*)d_in[9];
    float* out = (float*)d_out;

    __nv_bfloat16 *xs, *wtq, *wtk, *wtv, *wto, *qsp, *ksp, *vsp, *cs;
    cudaGetSymbolAddress((void**)&xs,  g_xs);
    cudaGetSymbolAddress((void**)&wtq, g_wtq);
    cudaGetSymbolAddress((void**)&wtk, g_wtk);
    cudaGetSymbolAddress((void**)&wtv, g_wtv);
    cudaGetSymbolAddress((void**)&wto, g_wto);
    cudaGetSymbolAddress((void**)&qsp, g_qsp);
    cudaGetSymbolAddress((void**)&ksp, g_ksp);
    cudaGetSymbolAddress((void**)&vsp, g_vsp);
    cudaGetSymbolAddress((void**)&cs,  g_cs);

    static bool attr_done = false;
    if (!attr_done) {
        cudaFuncSetAttribute(gemm_mma<0>, cudaFuncAttributeMaxDynamicSharedMemorySize, GEMM_SMEM);
        cudaFuncSetAttribute(gemm_mma<2>, cudaFuncAttributeMaxDynamicSharedMemorySize, GEMM_SMEM);
        cudaFuncSetAttribute(gemm_mma<3>, cudaFuncAttributeMaxDynamicSharedMemorySize, GEMM_SMEM);
        cudaFuncSetAttribute(attn_mma,    cudaFuncAttributeMaxDynamicSharedMemorySize, ATTN_SMEM);
        attr_done = true;
    }

    // 1: input split
    split_kernel<<<MTOT, 256>>>(x, xs);
    // 2: fused weight splits
    dim3 wgrid(32, 32, 4), wblock(32, 8);
    wsplit_kernel<<<wgrid, wblock>>>(Wq, Wk, Wv, Wo, wtq, wtk, wtv, wto);

    // 3-5: projections (frozen round-10 GEMM)
    dim3 ggrid(DMODEL / 128, MTOT / 128);     // (8, 64)
    gemm_mma<3><<<ggrid, 256, GEMM_SMEM>>>(xs, wtq, bq, qsp, rope_start, 0.125f);
    gemm_mma<3><<<ggrid, 256, GEMM_SMEM>>>(xs, wtk, bk, ksp, rope_start, 1.0f);
    gemm_mma<2><<<ggrid, 256, GEMM_SMEM>>>(xs, wtv, bv, vsp, rope_start, 1.0f);

    // 6: attention (3-stage ring, single sync, 2 CTA/SM)
    attn_mma<<<dim3(SEQ / 128, BATCH * NHEAD), 256, ATTN_SMEM>>>(qsp, ksp, vsp, cs);

    // 7: output projection
    gemm_mma<0><<<ggrid, 256, GEMM_SMEM>>>(cs, wto, bo, out, rope_start, 1.0f);
}

// round 17
// speedup vs baseline: 1.5504x; 1.0886x over previous
#include <cuda_runtime.h>
#include <cuda_bf16.h>
#include <cuda_fp16.h>
#include <math.h>
#include <stdint.h>

#define BATCH 4
#define SEQ   2048
#define DMODEL 1024
#define NHEAD 16
#define HDIM  64
#define MTOT  8192          // BATCH*SEQ
#define KSP   2048          // 2*DMODEL (hi|lo)

// ---------------- scratch (device globals) ----------------
__device__ __nv_bfloat16 g_xs[MTOT * KSP];                   // x split bf16 [M][2048] (Q,K)
__device__ __half        g_xsf[MTOT * KSP];                  // x split fp16 [M][2048] (V)
__device__ __nv_bfloat16 g_wtq[DMODEL * KSP];                // W^T split bf16 [N][2048]
__device__ __nv_bfloat16 g_wtk[DMODEL * KSP];
__device__ __half        g_wtv16[DMODEL * DMODEL];           // Wv^T fp16 [N][1024]
__device__ __half        g_wto16[DMODEL * DMODEL];           // Wo^T fp16 [N][1024]
__device__ __nv_bfloat16 g_qsp[BATCH * NHEAD * SEQ * 2 * HDIM]; // [B,H,S,128] hi|lo
__device__ __nv_bfloat16 g_ksp[BATCH * NHEAD * SEQ * 2 * HDIM];
__device__ __nv_bfloat16 g_vsp[BATCH * NHEAD * SEQ * 2 * HDIM];
__device__ __half        g_csf[MTOT * KSP];                  // ctx split fp16 [M][2048]

// ---------------- helpers ----------------
__device__ __forceinline__ uint32_t smem_u32(const void* p) {
    return (uint32_t)__cvta_generic_to_shared(p);
}
__device__ __forceinline__ void cp16(uint32_t s, const void* g) {
    asm volatile("cp.async.cg.shared.global [%0], [%1], 16;" :: "r"(s), "l"(g));
}
__device__ __forceinline__ void cp_commit() {
    asm volatile("cp.async.commit_group;" ::: "memory");
}
__device__ __forceinline__ void cp_wait1() {
    asm volatile("cp.async.wait_group 1;" ::: "memory");
}
__device__ __forceinline__ void cp_wait0() {
    asm volatile("cp.async.wait_group 0;" ::: "memory");
}
__device__ __forceinline__ void ldsm_x4(uint32_t& r0, uint32_t& r1, uint32_t& r2, uint32_t& r3, uint32_t a) {
    asm volatile("ldmatrix.sync.aligned.m8n8.x4.shared.b16 {%0,%1,%2,%3},[%4];"
                 : "=r"(r0), "=r"(r1), "=r"(r2), "=r"(r3) : "r"(a));
}
__device__ __forceinline__ void ldsm_x4t(uint32_t& r0, uint32_t& r1, uint32_t& r2, uint32_t& r3, uint32_t a) {
    asm volatile("ldmatrix.sync.aligned.m8n8.x4.trans.shared.b16 {%0,%1,%2,%3},[%4];"
                 : "=r"(r0), "=r"(r1), "=r"(r2), "=r"(r3) : "r"(a));
}
__device__ __forceinline__ void mma16816(float* c, const uint32_t* a, const uint32_t* b) {
    asm volatile(
        "mma.sync.aligned.m16n8k16.row.col.f32.bf16.bf16.f32 "
        "{%0,%1,%2,%3},{%4,%5,%6,%7},{%8,%9},{%0,%1,%2,%3};"
        : "+f"(c[0]), "+f"(c[1]), "+f"(c[2]), "+f"(c[3])
        : "r"(a[0]), "r"(a[1]), "r"(a[2]), "r"(a[3]), "r"(b[0]), "r"(b[1]));
}
__device__ __forceinline__ void mma16816h(float* c, const uint32_t* a, const uint32_t* b) {
    asm volatile(
        "mma.sync.aligned.m16n8k16.row.col.f32.f16.f16.f32 "
        "{%0,%1,%2,%3},{%4,%5,%6,%7},{%8,%9},{%0,%1,%2,%3};"
        : "+f"(c[0]), "+f"(c[1]), "+f"(c[2]), "+f"(c[3])
        : "r"(a[0]), "r"(a[1]), "r"(a[2]), "r"(a[3]), "r"(b[0]), "r"(b[1]));
}
__device__ __forceinline__ void pack_pair(float x0, float x1, uint32_t& hi, uint32_t& lo) {
    uint32_t h;
    asm("cvt.rn.bf16x2.f32 %0, %1, %2;" : "=r"(h) : "f"(x1), "f"(x0));
    __nv_bfloat162 h2 = *reinterpret_cast<__nv_bfloat162*>(&h);
    float r0 = x0 - __bfloat162float(h2.x);
    float r1 = x1 - __bfloat162float(h2.y);
    uint32_t l;
    asm("cvt.rn.bf16x2.f32 %0, %1, %2;" : "=r"(l) : "f"(r1), "f"(r0));
    hi = h; lo = l;
}
__device__ __forceinline__ void pack_pair_h(float x0, float x1, uint32_t& hi, uint32_t& lo) {
    __half2 h = __floats2half2_rn(x0, x1);
    float r0 = x0 - __half2float(__low2half(h));
    float r1 = x1 - __half2float(__high2half(h));
    __half2 l = __floats2half2_rn(r0, r1);
    hi = *reinterpret_cast<uint32_t*>(&h);
    lo = *reinterpret_cast<uint32_t*>(&l);
}

// ---------------- split: fp32 [M][1024] -> bf16-split + fp16-split [M][2048] ----------------
__global__ __launch_bounds__(256)
void split_kernel(const float* __restrict__ in,
                  __nv_bfloat16* __restrict__ outb,
                  __half* __restrict__ outh)
{
    int i = blockIdx.x * 256 + threadIdx.x;
    float4 x = reinterpret_cast<const float4*>(in)[i];
    int r = i >> 8;
    int c = (i & 255) * 4;
    // bf16 split
    __nv_bfloat162 h0 = __floats2bfloat162_rn(x.x, x.y);
    __nv_bfloat162 h1 = __floats2bfloat162_rn(x.z, x.w);
    __nv_bfloat162 l0 = __floats2bfloat162_rn(x.x - __bfloat162float(h0.x), x.y - __bfloat162float(h0.y));
    __nv_bfloat162 l1 = __floats2bfloat162_rn(x.z - __bfloat162float(h1.x), x.w - __bfloat162float(h1.y));
    __nv_bfloat162* oh = reinterpret_cast<__nv_bfloat162*>(&outb[(long)r * KSP + c]);
    oh[0] = h0; oh[1] = h1;
    __nv_bfloat162* ol = reinterpret_cast<__nv_bfloat162*>(&outb[(long)r * KSP + 1024 + c]);
    ol[0] = l0; ol[1] = l1;
    // fp16 split
    __half2 f0 = __floats2half2_rn(x.x, x.y);
    __half2 f1 = __floats2half2_rn(x.z, x.w);
    __half2 g0 = __floats2half2_rn(x.x - __half2float(__low2half(f0)), x.y - __half2float(__high2half(f0)));
    __half2 g1 = __floats2half2_rn(x.z - __half2float(__low2half(f1)), x.w - __half2float(__high2half(f1)));
    __half2* ph = reinterpret_cast<__half2*>(&outh[(long)r * KSP + c]);
    ph[0] = f0; ph[1] = f1;
    __half2* pl = reinterpret_cast<__half2*>(&outh[(long)r * KSP + 1024 + c]);
    pl[0] = g0; pl[1] = g1;
}

// ---------------- fused weight prep: Wq/Wk bf16 split; Wv/Wo fp16 unsplit ----------------
__global__ void wsplit_kernel(const float* __restrict__ W0, const float* __restrict__ W1,
                              const float* __restrict__ W2, const float* __restrict__ W3,
                              __nv_bfloat16* __restrict__ T0, __nv_bfloat16* __restrict__ T1,
                              __half* __restrict__ H2, __half* __restrict__ H3)
{
    const int z = blockIdx.z;
    const float* W = (z == 0) ? W0 : (z == 1) ? W1 : (z == 2) ? W2 : W3;

    __shared__ float tile[32][33];
    int n0 = blockIdx.x * 32, k0 = blockIdx.y * 32;
    int tx = threadIdx.x, ty = threadIdx.y;   // 32 x 8
#pragma unroll
    for (int j = 0; j < 4; j++)
        tile[ty + 8 * j][tx] = W[(long)(k0 + ty + 8 * j) * DMODEL + n0 + tx];
    __syncthreads();
#pragma unroll
    for (int j = 0; j < 4; j++) {
        int n = n0 + ty + 8 * j;
        int k = k0 + tx;
        float v = tile[tx][ty + 8 * j];
        if (z < 2) {
            __nv_bfloat16* Wt = (z == 0) ? T0 : T1;
            __nv_bfloat16 h = __float2bfloat16(v);
            Wt[(long)n * KSP + k] = h;
            Wt[(long)n * KSP + 1024 + k] = __float2bfloat16(v - __bfloat162float(h));
        } else {
            __half* Wt = (z == 2) ? H2 : H3;
            Wt[(long)n * DMODEL + k] = __float2half(v);
        }
    }
}

// ---------------- bf16 split 3-pass GEMM (frozen round-10; Q,K projections) ----------------
#define NSTEP 48
#define GPAD  72
#define GEMM_SMEM (3 * 128 * GPAD * 2 * 2)

__global__ __launch_bounds__(256, 2)
void gemm_mma(const __nv_bfloat16* __restrict__ A,
              const __nv_bfloat16* __restrict__ Bt,
              const float* __restrict__ bias,
              __nv_bfloat16* __restrict__ Cout,   // heads split + rope + scale
              const int* __restrict__ start_p,
              float scale)
{
    extern __shared__ __align__(16) char smem_raw[];
    __nv_bfloat16* sA = reinterpret_cast<__nv_bfloat16*>(smem_raw);
    __nv_bfloat16* sB = sA + 3 * 128 * GPAD;

    const int tid = threadIdx.x;
    const int lane = tid & 31;
    const int wid = tid >> 5;
    const int warp_m = wid & 1;
    const int warp_n = wid >> 1;
    const int m0 = blockIdx.y * 128;
    const int n0 = blockIdx.x * 128;

    float acc[4][4][4];
#pragma unroll
    for (int i = 0; i < 4; i++)
#pragma unroll
        for (int j = 0; j < 4; j++)
#pragma unroll
            for (int q = 0; q < 4; q++) acc[i][j][q] = 0.f;

    const int ldrow = tid >> 3;
    const int ldc8  = tid & 7;

    auto issue = [&](int st, int step) {
        const int seg = step >> 4;
        const int ks  = (step & 15) << 6;
        const int aoff = (seg == 1 ? 1024 : 0) + ks;
        const int boff = (seg == 2 ? 1024 : 0) + ks;
        __nv_bfloat16* sAs = sA + st * 128 * GPAD;
        __nv_bfloat16* sBs = sB + st * 128 * GPAD;
#pragma unroll
        for (int i = 0; i < 4; i++) {
            const int r = ldrow + 32 * i;
            cp16(smem_u32(&sAs[r * GPAD + ldc8 * 8]),
                 &A[(long)(m0 + r) * KSP + aoff + ldc8 * 8]);
            cp16(smem_u32(&sBs[r * GPAD + ldc8 * 8]),
                 &Bt[(long)(n0 + r) * KSP + boff + ldc8 * 8]);
        }
    };

    issue(0, 0); cp_commit();
    issue(1, 1); cp_commit();

    for (int step = 0; step < NSTEP; step++) {
        if (step == NSTEP - 1) cp_wait0(); else cp_wait1();
        __syncthreads();
        if (step + 2 < NSTEP) { issue((step + 2) % 3, step + 2); cp_commit(); }

        const int st = step % 3;
        const __nv_bfloat16* sAs = sA + st * 128 * GPAD;
        const __nv_bfloat16* sBs = sB + st * 128 * GPAD;

#pragma unroll
        for (int kk = 0; kk < 64; kk += 16) {
            uint32_t af[4][4];
            const int mrow = warp_m * 64 + (lane & 15);
            const int kcol = kk + ((lane >> 4) << 3);
#pragma unroll
            for (int mt = 0; mt < 4; mt++)
                ldsm_x4(af[mt][0], af[mt][1], af[mt][2], af[mt][3],
                        smem_u32(&sAs[(mrow + mt * 16) * GPAD + kcol]));
            uint32_t bfr[4][2];
#pragma unroll
            for (int bt = 0; bt < 2; bt++) {
                int n = warp_n * 32 + bt * 16 + ((lane >> 4) << 3) + (lane & 7);
                int kc2 = kk + (((lane >> 3) & 1) << 3);
                uint32_t r0, r1, r2, r3;
                ldsm_x4(r0, r1, r2, r3, smem_u32(&sBs[n * GPAD + kc2]));
                bfr[2 * bt][0] = r0; bfr[2 * bt][1] = r1;
                bfr[2 * bt + 1][0] = r2; bfr[2 * bt + 1][1] = r3;
            }
#pragma unroll
            for (int mt = 0; mt < 4; mt++)
#pragma unroll
                for (int nt = 0; nt < 4; nt++)
                    mma16816(acc[mt][nt], af[mt], bfr[nt]);
        }
    }

    // epilogue: heads split + rope + scale
    const int r_m = warp_m * 64 + (lane >> 2);
    const int c_n = warp_n * 32 + 2 * (lane & 3);
    const int start = *start_p;

#pragma unroll
    for (int mt = 0; mt < 4; mt++) {
#pragma unroll
        for (int nt = 0; nt < 4; nt++) {
            const int mg = m0 + r_m + mt * 16;
            const int ng = n0 + c_n + nt * 8;
            const float b0v = bias[ng], b1v = bias[ng + 1];
            float x0 = acc[mt][nt][0] + b0v, x1 = acc[mt][nt][1] + b1v;
            float y0 = acc[mt][nt][2] + b0v, y1 = acc[mt][nt][3] + b1v;

            const int b = mg >> 11, s = mg & (SEQ - 1);
            const int h = ng >> 6, d = ng & (HDIM - 1);
            const long rowb = ((long)(b * NHEAD + h) * SEQ + s) * 128;
#pragma unroll
            for (int rr = 0; rr < 2; rr++) {
                float v0 = rr ? y0 : x0;
                float v1 = rr ? y1 : x1;
                int ss = s + rr * 8;
                if (ss >= start) {
                    float pos = (float)(ss - start);
                    float invf = __expf(-(float)(d >> 1) * 0.28782313662425572f);
                    float sn, cs;
                    sincosf(pos * invf, &sn, &cs);
                    float t0 = v0 * cs - v1 * sn;
                    float t1 = v1 * cs + v0 * sn;
                    v0 = t0; v1 = t1;
                }
                v0 *= scale; v1 *= scale;
                uint32_t hi, lo;
                pack_pair(v0, v1, hi, lo);
                long ro = rowb + (long)rr * 8 * 128;
                *(uint32_t*)&Cout[ro + d] = hi;
                *(uint32_t*)&Cout[ro + 64 + d] = lo;
            }
        }
    }
}

// ---------------- fp16 2-pass GEMM (A split fp16, B unsplit fp16; V & out projections) ----------------
// K-space = 2 segments x 1024: Ahi*B + Alo*B. 32 steps, same frozen 3-stage structure.
#define NSTEP16 32

template <int OUT_MODE>   // 0: fp32 [M][N]; 2: heads bf16-split (no rope)
__global__ __launch_bounds__(256, 2)
void gemm_f16(const __half* __restrict__ A,
              const __half* __restrict__ Bt,
              const float* __restrict__ bias,
              void* __restrict__ Cout)
{
    extern __shared__ __align__(16) char smem_raw[];
    __half* sA = reinterpret_cast<__half*>(smem_raw);
    __half* sB = sA + 3 * 128 * GPAD;

    const int tid = threadIdx.x;
    const int lane = tid & 31;
    const int wid = tid >> 5;
    const int warp_m = wid & 1;
    const int warp_n = wid >> 1;
    const int m0 = blockIdx.y * 128;
    const int n0 = blockIdx.x * 128;

    float acc[4][4][4];
#pragma unroll
    for (int i = 0; i < 4; i++)
#pragma unroll
        for (int j = 0; j < 4; j++)
#pragma unroll
            for (int q = 0; q < 4; q++) acc[i][j][q] = 0.f;

    const int ldrow = tid >> 3;
    const int ldc8  = tid & 7;

    auto issue = [&](int st, int step) {
        const int seg = step >> 4;          // 0: Ahi, 1: Alo
        const int ks  = (step & 15) << 6;
        const int aoff = seg * 1024 + ks;
        __half* sAs = sA + st * 128 * GPAD;
        __half* sBs = sB + st * 128 * GPAD;
#pragma unroll
        for (int i = 0; i < 4; i++) {
            const int r = ldrow + 32 * i;
            cp16(smem_u32(&sAs[r * GPAD + ldc8 * 8]),
                 &A[(long)(m0 + r) * KSP + aoff + ldc8 * 8]);
            cp16(smem_u32(&sBs[r * GPAD + ldc8 * 8]),
                 &Bt[(long)(n0 + r) * DMODEL + ks + ldc8 * 8]);
        }
    };

    issue(0, 0); cp_commit();
    issue(1, 1); cp_commit();

    for (int step = 0; step < NSTEP16; step++) {
        if (step == NSTEP16 - 1) cp_wait0(); else cp_wait1();
        __syncthreads();
        if (step + 2 < NSTEP16) { issue((step + 2) % 3, step + 2); cp_commit(); }

        const int st = step % 3;
        const __half* sAs = sA + st * 128 * GPAD;
        const __half* sBs = sB + st * 128 * GPAD;

#pragma unroll
        for (int kk = 0; kk < 64; kk += 16) {
            uint32_t af[4][4];
            const int mrow = warp_m * 64 + (lane & 15);
            const int kcol = kk + ((lane >> 4) << 3);
#pragma unroll
            for (int mt = 0; mt < 4; mt++)
                ldsm_x4(af[mt][0], af[mt][1], af[mt][2], af[mt][3],
                        smem_u32(&sAs[(mrow + mt * 16) * GPAD + kcol]));
            uint32_t bfr[4][2];
#pragma unroll
            for (int bt = 0; bt < 2; bt++) {
                int n = warp_n * 32 + bt * 16 + ((lane >> 4) << 3) + (lane & 7);
                int kc2 = kk + (((lane >> 3) & 1) << 3);
                uint32_t r0, r1, r2, r3;
                ldsm_x4(r0, r1, r2, r3, smem_u32(&sBs[n * GPAD + kc2]));
                bfr[2 * bt][0] = r0; bfr[2 * bt][1] = r1;
                bfr[2 * bt + 1][0] = r2; bfr[2 * bt + 1][1] = r3;
            }
#pragma unroll
            for (int mt = 0; mt < 4; mt++)
#pragma unroll
                for (int nt = 0; nt < 4; nt++)
                    mma16816h(acc[mt][nt], af[mt], bfr[nt]);
        }
    }

    // epilogue
    const int r_m = warp_m * 64 + (lane >> 2);
    const int c_n = warp_n * 32 + 2 * (lane & 3);

#pragma unroll
    for (int mt = 0; mt < 4; mt++) {
#pragma unroll
        for (int nt = 0; nt < 4; nt++) {
            const int mg = m0 + r_m + mt * 16;
            const int ng = n0 + c_n + nt * 8;
            const float b0v = bias[ng], b1v = bias[ng + 1];
            float x0 = acc[mt][nt][0] + b0v, x1 = acc[mt][nt][1] + b1v;
            float y0 = acc[mt][nt][2] + b0v, y1 = acc[mt][nt][3] + b1v;

            if (OUT_MODE == 0) {
                float* outp = (float*)Cout;
                *(float2*)&outp[(long)mg * DMODEL + ng] = make_float2(x0, x1);
                *(float2*)&outp[(long)(mg + 8) * DMODEL + ng] = make_float2(y0, y1);
            } else {
                const int b = mg >> 11, s = mg & (SEQ - 1);
                const int h = ng >> 6, d = ng & (HDIM - 1);
                const long rowb = ((long)(b * NHEAD + h) * SEQ + s) * 128;
                __nv_bfloat16* outp = (__nv_bfloat16*)Cout;
#pragma unroll
                for (int rr = 0; rr < 2; rr++) {
                    float v0 = rr ? y0 : x0;
                    float v1 = rr ? y1 : x1;
                    uint32_t hi, lo;
                    pack_pair(v0, v1, hi, lo);
                    long ro = rowb + (long)rr * 8 * 128;
                    *(uint32_t*)&outp[ro + d] = hi;
                    *(uint32_t*)&outp[ro + 64 + d] = lo;
                }
            }
        }
    }
}

// ---------------- flash attention (round-10 frozen; ctx written as fp16 split) ----------------
#define APAD 136
#define ATTN_STAGES 2
#define ATTN_SMEM (ATTN_STAGES * 64 * APAD * 2 * 2)

__global__ __launch_bounds__(256, 2)
void attn_mma(const __nv_bfloat16* __restrict__ qs,
              const __nv_bfloat16* __restrict__ ks,
              const __nv_bfloat16* __restrict__ vs,
              __half* __restrict__ cs)
{
    extern __shared__ __align__(16) char smem_raw[];
    __nv_bfloat16* sK = reinterpret_cast<__nv_bfloat16*>(smem_raw);   // [2][64][136]
    __nv_bfloat16* sV = sK + ATTN_STAGES * 64 * APAD;                 // [2][64][136]

    const int tid = threadIdx.x;
    const int lane = tid & 31;
    const int wid = tid >> 5;
    const int qb = blockIdx.x;
    const int bh = blockIdx.y;
    const long hbase = (long)bh * SEQ * 128;

    {
        const __nv_bfloat16* qg = qs + hbase + (long)qb * 128 * 128;
        const int r = tid >> 1;
        const int c = (tid & 1) * 64;
#pragma unroll
        for (int i = 0; i < 8; i++)
            *(uint4*)&sK[r * APAD + c + i * 8] = *(const uint4*)&qg[(long)r * 128 + c + i * 8];
    }
    __syncthreads();
    uint32_t qhi[4][4], qlo[4][4];
    {
        const int mrow = wid * 16 + (lane & 15);
        const int kadd = (lane >> 4) << 3;
#pragma unroll
        for (int kc = 0; kc < 4; kc++) {
            ldsm_x4(qhi[kc][0], qhi[kc][1], qhi[kc][2], qhi[kc][3],
                    smem_u32(&sK[mrow * APAD + kc * 16 + kadd]));
            ldsm_x4(qlo[kc][0], qlo[kc][1], qlo[kc][2], qlo[kc][3],
                    smem_u32(&sK[mrow * APAD + 64 + kc * 16 + kadd]));
        }
    }
    __syncthreads();

    const int ldrow  = tid >> 4;
    const int ldc16  = tid & 15;
    auto issue = [&](int st, int kt) {
        const __nv_bfloat16* kg = ks + hbase + (long)kt * 64 * 128;
        const __nv_bfloat16* vg = vs + hbase + (long)kt * 64 * 128;
        __nv_bfloat16* sKs = sK + st * 64 * APAD;
        __nv_bfloat16* sVs = sV + st * 64 * APAD;
#pragma unroll
        for (int i = 0; i < 4; i++) {
            const int r = ldrow + 16 * i;
            cp16(smem_u32(&sKs[r * APAD + ldc16 * 8]), &kg[(long)r * 128 + ldc16 * 8]);
            cp16(smem_u32(&sVs[r * APAD + ldc16 * 8]), &vg[(long)r * 128 + ldc16 * 8]);
        }
    };

    float O[8][4];
#pragma unroll
    for (int i = 0; i < 8; i++)
#pragma unroll
        for (int j = 0; j < 4; j++) O[i][j] = 0.f;
    float m0 = -1e30f, m1 = -1e30f, l0 = 0.f, l1 = 0.f;

    issue(0, 0); cp_commit();
    issue(1, 1); cp_commit();

    const int NT = SEQ / 64;
    for (int kt = 0; kt < NT; kt++) {
        if (kt >= NT - 1) cp_wait0(); else cp_wait1();
        __syncthreads();

        const int st = kt & 1;
        const __nv_bfloat16* Kst = sK + st * 64 * APAD;
        const __nv_bfloat16* Vst = sV + st * 64 * APAD;

        float S[8][4];
#pragma unroll
        for (int i = 0; i < 8; i++)
#pragma unroll
            for (int j = 0; j < 4; j++) S[i][j] = 0.f;

#pragma unroll
        for (int kc = 0; kc < 4; kc++) {
            uint32_t b4[4][4];
#pragma unroll
            for (int bt = 0; bt < 4; bt++) {
                int n = bt * 16 + ((lane >> 4) << 3) + (lane & 7);
                int kcol = kc * 16 + (((lane >> 3) & 1) << 3);
                ldsm_x4(b4[bt][0], b4[bt][1], b4[bt][2], b4[bt][3],
                        smem_u32(&Kst[n * APAD + kcol]));
            }
#pragma unroll
            for (int bt = 0; bt < 4; bt++) {
                mma16816(S[2 * bt],     qhi[kc], &b4[bt][0]);
                mma16816(S[2 * bt + 1], qhi[kc], &b4[bt][2]);
                mma16816(S[2 * bt],     qlo[kc], &b4[bt][0]);
                mma16816(S[2 * bt + 1], qlo[kc], &b4[bt][2]);
            }
        }
#pragma unroll
        for (int kc = 0; kc < 4; kc++) {
            uint32_t b4[4][4];
#pragma unroll
            for (int bt = 0; bt < 4; bt++) {
                int n = bt * 16 + ((lane >> 4) << 3) + (lane & 7);
                int kcol = 64 + kc * 16 + (((lane >> 3) & 1) << 3);
                ldsm_x4(b4[bt][0], b4[bt][1], b4[bt][2], b4[bt][3],
                        smem_u32(&Kst[n * APAD + kcol]));
            }
#pragma unroll
            for (int bt = 0; bt < 4; bt++) {
                mma16816(S[2 * bt],     qhi[kc], &b4[bt][0]);
                mma16816(S[2 * bt + 1], qhi[kc], &b4[bt][2]);
            }
        }

        float tmax0 = -1e30f, tmax1 = -1e30f;
#pragma unroll
        for (int nt = 0; nt < 8; nt++) {
            tmax0 = fmaxf(tmax0, fmaxf(S[nt][0], S[nt][1]));
            tmax1 = fmaxf(tmax1, fmaxf(S[nt][2], S[nt][3]));
        }
        tmax0 = fmaxf(tmax0, __shfl_xor_sync(0xffffffffu, tmax0, 1));
        tmax0 = fmaxf(tmax0, __shfl_xor_sync(0xffffffffu, tmax0, 2));
        tmax1 = fmaxf(tmax1, __shfl_xor_sync(0xffffffffu, tmax1, 1));
        tmax1 = fmaxf(tmax1, __shfl_xor_sync(0xffffffffu, tmax1, 2));
        const float mn0 = fmaxf(m0, tmax0);
        const float mn1 = fmaxf(m1, tmax1);
        const float corr0 = __expf(m0 - mn0);
        const float corr1 = __expf(m1 - mn1);
        m0 = mn0; m1 = mn1;
#pragma unroll
        for (int nt = 0; nt < 8; nt++) {
            O[nt][0] *= corr0; O[nt][1] *= corr0;
            O[nt][2] *= corr1; O[nt][3] *= corr1;
        }

        float sum0 = 0.f, sum1 = 0.f;
        uint32_t phi[4][4], plo[4][4];
#pragma unroll
        for (int bt = 0; bt < 4; bt++) {
            float p00 = __expf(S[2 * bt][0] - mn0), p01 = __expf(S[2 * bt][1] - mn0);
            float p02 = __expf(S[2 * bt][2] - mn1), p03 = __expf(S[2 * bt][3] - mn1);
            float p10 = __expf(S[2 * bt + 1][0] - mn0), p11 = __expf(S[2 * bt + 1][1] - mn0);
            float p12 = __expf(S[2 * bt + 1][2] - mn1), p13 = __expf(S[2 * bt + 1][3] - mn1);
            sum0 += p00 + p01 + p10 + p11;
            sum1 += p02 + p03 + p12 + p13;
            pack_pair(p00, p01, phi[bt][0], plo[bt][0]);
            pack_pair(p02, p03, phi[bt][1], plo[bt][1]);
            pack_pair(p10, p11, phi[bt][2], plo[bt][2]);
            pack_pair(p12, p13, phi[bt][3], plo[bt][3]);
        }
        sum0 += __shfl_xor_sync(0xffffffffu, sum0, 1);
        sum0 += __shfl_xor_sync(0xffffffffu, sum0, 2);
        sum1 += __shfl_xor_sync(0xffffffffu, sum1, 1);
        sum1 += __shfl_xor_sync(0xffffffffu, sum1, 2);
        l0 = l0 * corr0 + sum0;
        l1 = l1 * corr1 + sum1;

#pragma unroll
        for (int kc = 0; kc < 4; kc++) {
            uint32_t vb[4][4];
#pragma unroll
            for (int ntp = 0; ntp < 4; ntp++) {
                int key = kc * 16 + ((lane >> 3) & 1) * 8 + (lane & 7);
                int col = ntp * 16 + ((lane >> 4) << 3);
                ldsm_x4t(vb[ntp][0], vb[ntp][1], vb[ntp][2], vb[ntp][3],
                         smem_u32(&Vst[key * APAD + col]));
            }
#pragma unroll
            for (int ntp = 0; ntp < 4; ntp++) {
                mma16816(O[2 * ntp],     phi[kc], &vb[ntp][0]);
                mma16816(O[2 * ntp + 1], phi[kc], &vb[ntp][2]);
                mma16816(O[2 * ntp],     plo[kc], &vb[ntp][0]);
                mma16816(O[2 * ntp + 1], plo[kc], &vb[ntp][2]);
            }
        }
#pragma unroll
        for (int kc = 0; kc < 4; kc++) {
            uint32_t vb[4][4];
#pragma unroll
            for (int ntp = 0; ntp < 4; ntp++) {
                int key = kc * 16 + ((lane >> 3) & 1) * 8 + (lane & 7);
                int col = 64 + ntp * 16 + ((lane >> 4) << 3);
                ldsm_x4t(vb[ntp][0], vb[ntp][1], vb[ntp][2], vb[ntp][3],
                         smem_u32(&Vst[key * APAD + col]));
            }
#pragma unroll
            for (int ntp = 0; ntp < 4; ntp++) {
                mma16816(O[2 * ntp],     phi[kc], &vb[ntp][0]);
                mma16816(O[2 * ntp + 1], phi[kc], &vb[ntp][2]);
            }
        }

        __syncthreads();
        if (kt + 2 < NT) { issue(st, kt + 2); cp_commit(); }
    }

    // write ctx as fp16 split: cs[M][2048]
    const float inv0 = 1.f / l0;
    const float inv1 = 1.f / l1;
    const int b = bh >> 4, h = bh & 15;
    const int s0 = qb * 128 + wid * 16 + (lane >> 2);
    const long row0 = (long)(b * SEQ + s0) * KSP;
    const long row1 = row0 + (long)8 * KSP;
#pragma unroll
    for (int nt = 0; nt < 8; nt++) {
        int c = h * HDIM + nt * 8 + 2 * (lane & 3);
        uint32_t hi, lo;
        pack_pair_h(O[nt][0] * inv0, O[nt][1] * inv0, hi, lo);
        *(uint32_t*)&cs[row0 + c] = hi;
        *(uint32_t*)&cs[row0 + 1024 + c] = lo;
        pack_pair_h(O[nt][2] * inv1, O[nt][3] * inv1, hi, lo);
        *(uint32_t*)&cs[row1 + c] = hi;
        *(uint32_t*)&cs[row1 + 1024 + c] = lo;
    }
}

// ---------------- launch ----------------
extern "C" void kernel_launch(void* const* d_in, const int* in_sizes, int n_in,
                              void* d_out, int out_size)
{
    const float* x  = (const float*)d_in[0];
    const float* Wq = (const float*)d_in[1];
    const float* bq = (const float*)d_in[2];
    const float* Wk = (const float*)d_in[3];
    const float* bk = (const float*)d_in[4];
    const float* Wv = (const float*)d_in[5];
    const float* bv = (const float*)d_in[6];
    const float* Wo = (const float*)d_in[7];
    const float* bo = (const float*)d_in[8];
    const int* rope_start = (const int*)d_in[9];
    float* out = (float*)d_out;

    __nv_bfloat16 *xs, *wtq, *wtk, *qsp, *ksp, *vsp;
    __half *xsf, *wtv16, *wto16, *csf;
    cudaGetSymbolAddress((void**)&xs,    g_xs);
    cudaGetSymbolAddress((void**)&xsf,   g_xsf);
    cudaGetSymbolAddress((void**)&wtq,   g_wtq);
    cudaGetSymbolAddress((void**)&wtk,   g_wtk);
    cudaGetSymbolAddress((void**)&wtv16, g_wtv16);
    cudaGetSymbolAddress((void**)&wto16, g_wto16);
    cudaGetSymbolAddress((void**)&qsp,   g_qsp);
    cudaGetSymbolAddress((void**)&ksp,   g_ksp);
    cudaGetSymbolAddress((void**)&vsp,   g_vsp);
    cudaGetSymbolAddress((void**)&csf,   g_csf);

    static bool attr_done = false;
    if (!attr_done) {
        cudaFuncSetAttribute(gemm_mma,    cudaFuncAttributeMaxDynamicSharedMemorySize, GEMM_SMEM);
        cudaFuncSetAttribute(gemm_f16<0>, cudaFuncAttributeMaxDynamicSharedMemorySize, GEMM_SMEM);
        cudaFuncSetAttribute(gemm_f16<2>, cudaFuncAttributeMaxDynamicSharedMemorySize, GEMM_SMEM);
        cudaFuncSetAttribute(attn_mma,    cudaFuncAttributeMaxDynamicSharedMemorySize, ATTN_SMEM);
        attr_done = true;
    }

    // 1: input split (bf16 + fp16)
    split_kernel<<<MTOT, 256>>>(x, xs, xsf);
    // 2: fused weight prep
    dim3 wgrid(32, 32, 4), wblock(32, 8);
    wsplit_kernel<<<wgrid, wblock>>>(Wq, Wk, Wv, Wo, wtq, wtk, wtv16, wto16);

    // 3-4: Q,K projections (bf16 3-pass, rope+scale)
    dim3 ggrid(DMODEL / 128, MTOT / 128);     // (8, 64)
    gemm_mma<<<ggrid, 256, GEMM_SMEM>>>(xs, wtq, bq, qsp, rope_start, 0.125f);
    gemm_mma<<<ggrid, 256, GEMM_SMEM>>>(xs, wtk, bk, ksp, rope_start, 1.0f);
    // 5: V projection (fp16 2-pass)
    gemm_f16<2><<<ggrid, 256, GEMM_SMEM>>>(xsf, wtv16, bv, vsp);

    // 6: attention (2-stage, 2 CTA/SM, fp16-split ctx output)
    attn_mma<<<dim3(SEQ / 128, BATCH * NHEAD), 256, ATTN_SMEM>>>(qsp, ksp, vsp, csf);

    // 7: output projection (fp16 2-pass)
    gemm_f16<0><<<ggrid, 256, GEMM_SMEM>>>(csf, wto16, bo, out);
}